// round 11
// baseline (speedup 1.0000x reference)
#include <cuda_runtime.h>
#include <math.h>

#define BB 2
#define NN 512
#define QDIM 512
#define EDIM 11
#define NH 4
#define DHEAD 64
#define DIN 256          // INNER = NH*DHEAD
#define SCALE_F 0.125f   // 64^-0.5
#define NEGMAX -3.402823466e38f

#define ITILE 2
#define JTILE 32
#define ESTRIDE 12       // padded edge-feature row stride

// -------- device scratch (no allocations allowed) --------
__device__ float g_q[BB * NN * DIN];
__device__ float g_k[BB * NN * DIN];
__device__ float g_v[BB * NN * DIN];
__device__ float g_oi[BB * NN * DIN];
__device__ float g_attn_scratch[BB * NH * NN * NN];
__device__ unsigned char g_mask[BB * NN * NN];

typedef unsigned long long u64;

// ---- packed fp32x2 helpers ----
__device__ __forceinline__ u64 pack2(float lo, float hi) {
    u64 r; asm("mov.b64 %0, {%1, %2};" : "=l"(r) : "f"(lo), "f"(hi)); return r;
}
__device__ __forceinline__ void unpack2(u64 v, float& lo, float& hi) {
    asm("mov.b64 {%0, %1}, %2;" : "=f"(lo), "=f"(hi) : "l"(v));
}
__device__ __forceinline__ u64 fma2(u64 a, u64 b, u64 c) {
    u64 d; asm("fma.rn.f32x2 %0, %1, %2, %3;" : "=l"(d) : "l"(a), "l"(b), "l"(c)); return d;
}

// lean fast GELU (validated: total rel_err ~5e-7)
__device__ __forceinline__ float gelu_fast(float x) {
    float x2 = x * x;
    float u = x * fmaf(0.0356774081f, x2, 0.7978845608f);
    float th;
    asm("tanh.approx.f32 %0, %1;" : "=f"(th) : "f"(u));
    float hx = 0.5f * x;
    return fmaf(hx, th, hx);
}

// ============================================================
// Mask canonicalization with embedded dtype detection (proven).
// ============================================================
__global__ __launch_bounds__(256) void canon_mask_kernel(
    const unsigned int* __restrict__ raw, int n)
{
    int weird = 0, flt = 0;
    for (int i = threadIdx.x; i < 4096; i += 256) {
        unsigned int v = raw[i];
        if (v == 0x3F800000u) flt = 1;
        else if (v > 1u) weird = 1;
    }
    weird = __syncthreads_or(weird);
    flt   = __syncthreads_or(flt);
    const int mode = weird ? 2 : (flt ? 1 : 0);

    for (int i = blockIdx.x * blockDim.x + threadIdx.x; i < n; i += gridDim.x * blockDim.x) {
        unsigned char m;
        if (mode == 2)      m = (((const unsigned char*)raw)[i] != 0);
        else if (mode == 1) m = (((const float*)raw)[i] != 0.0f);
        else                m = (raw[i] != 0u);
        g_mask[i] = m;
    }
}

// ============================================================
// GEMM 64x32 tile, 256 threads, 4x2 per thread, K-tile 16.
// ============================================================
__device__ __forceinline__ void gemm_body(
    const float* __restrict__ A, const float* __restrict__ W,
    const float* __restrict__ bias, float* __restrict__ C,
    int M, int K, int Nc, int m0, int n0)
{
    __shared__ float As[16][65];
    __shared__ float Bs[16][33];
    const int t = threadIdx.x;
    const int r = t >> 4, c = t & 15;
    float acc[4][2] = {};

    for (int k0 = 0; k0 < K; k0 += 16) {
        #pragma unroll
        for (int l = 0; l < 4; l++) {
            int idx = t + l * 256;
            int mm = idx >> 4, kk = idx & 15;
            As[kk][mm] = A[(m0 + mm) * K + (k0 + kk)];
        }
        #pragma unroll
        for (int l = 0; l < 2; l++) {
            int idx = t + l * 256;
            int kk = idx >> 5, nn = idx & 31;
            Bs[kk][nn] = W[(k0 + kk) * Nc + (n0 + nn)];
        }
        __syncthreads();
        #pragma unroll
        for (int kk = 0; kk < 16; kk++) {
            float av[4], bv[2];
            #pragma unroll
            for (int l = 0; l < 4; l++) av[l] = As[kk][r * 4 + l];
            bv[0] = Bs[kk][c * 2];
            bv[1] = Bs[kk][c * 2 + 1];
            #pragma unroll
            for (int i = 0; i < 4; i++) {
                acc[i][0] += av[i] * bv[0];
                acc[i][1] += av[i] * bv[1];
            }
        }
        __syncthreads();
    }

    #pragma unroll
    for (int i = 0; i < 4; i++)
        #pragma unroll
        for (int j = 0; j < 2; j++) {
            int m = m0 + r * 4 + i, n = n0 + c * 2 + j;
            float v = acc[i][j];
            if (bias) v += bias[n];
            C[m * Nc + n] = v;
        }
}

__global__ __launch_bounds__(256) void qkv_gemm(
    const float* __restrict__ x,
    const float* __restrict__ Wq, const float* __restrict__ Wk, const float* __restrict__ Wv)
{
    const int sel = blockIdx.x >> 3;
    const int n0 = (blockIdx.x & 7) * 32;
    const int m0 = blockIdx.y * 64;
    const float* W = (sel == 0) ? Wq : (sel == 1) ? Wk : Wv;
    float* C = (sel == 0) ? g_q : (sel == 1) ? g_k : g_v;
    gemm_body(x, W, nullptr, C, BB * NN, QDIM, DIN, m0, n0);
}

__global__ __launch_bounds__(256) void gemm_tiled(
    const float* __restrict__ A, const float* __restrict__ W,
    const float* __restrict__ bias, float* __restrict__ C,
    int M, int K, int Nc)
{
    gemm_body(A, W, bias, C, M, K, Nc, blockIdx.y * 64, blockIdx.x * 32);
}

// ============================================================
// Fused attention: block = (b, 2 query rows), 256 threads,
// FOUR warps per row (64-channel quarters), 3 blocks/SM target.
// smem (floats): qs/vacc 0..512 | S 512..4608 | tsh 4608..6656 |
//   esh 6656..7424 | kvs 7424..15616 | S2t 15616..16384 |
//   msh bytes @16384 (+256 floats). total 16640 fl = 66560 B.
// ============================================================
__global__ __launch_bounds__(256, 3) void attn_fused(
    const float* __restrict__ edge_attr,
    const unsigned char* __restrict__ mask,
    const float* __restrict__ Web1, const float* __restrict__ beb1,
    const float* __restrict__ Web2, const float* __restrict__ beb2,
    const float* __restrict__ Wev1, const float* __restrict__ bev1,
    const float* __restrict__ Wev2, const float* __restrict__ bev2,
    float* __restrict__ attn_out)
{
    extern __shared__ float sm[];
    float* qs   = sm;                   // 512 (2*256), reused as vacc
    float* vacc = sm;
    float* S    = sm + 512;             // 4096 (2 rows * 4 heads * 512)
    float* tsh  = sm + 4608;            // 2048 (2*4*256)
    float* esh  = sm + 6656;            // 768  (2*32*ESTRIDE)
    float* kvs  = sm + 7424;            // 8192 (32*256)
    float* S2t  = sm + 15616;           // 768  (3 quarters * 2*4*32)
    unsigned char* msh = (unsigned char*)(sm + 16384);  // 1024 B

    const int t = threadIdx.x;
    const int warp = t >> 5, lane = t & 31;
    const int b = blockIdx.y;
    const int i0 = blockIdx.x * ITILE;
    const int ii = warp >> 2;    // query row (0..1)
    const int qch = warp & 3;    // channel quarter (0..3)
    const int hsel = lane >> 3;  // head finalized by this lane
    const int lead = ((lane & 7) == 0);

    // ---- stage q rows (512 floats) + mask rows (1024 B) ----
    if (t < 128) ((float4*)qs)[t] = ((const float4*)&g_q[(b * NN + i0) * DIN])[t];
    ((unsigned int*)msh)[t] = ((const unsigned int*)&mask[(b * NN + i0) * NN])[t];

    // ---- per-lane packed weights: ONE chain (channels cc0, cc0+32) ----
    u64 W1p[EDIM], b1p, W2p[2][2];
    {
        int cc0 = qch * 64 + lane;
        int cc1 = cc0 + 32;
        b1p = pack2(beb1[cc0], beb1[cc1]);
        #pragma unroll
        for (int a = 0; a < EDIM; a++)
            W1p[a] = pack2(Web1[a * DIN + cc0], Web1[a * DIN + cc1]);
        W2p[0][0] = pack2(Web2[cc0 * NH + 0], Web2[cc0 * NH + 1]);
        W2p[0][1] = pack2(Web2[cc0 * NH + 2], Web2[cc0 * NH + 3]);
        W2p[1][0] = pack2(Web2[cc1 * NH + 0], Web2[cc1 * NH + 1]);
        W2p[1][1] = pack2(Web2[cc1 * NH + 2], Web2[cc1 * NH + 3]);
    }
    const float b2h = beb2[hsel];
    __syncthreads();

    // hoist this row's q into registers (qch==0 warps compute qk)
    float qreg[NH][2];
    if (qch == 0) {
        #pragma unroll
        for (int h = 0; h < NH; h++) {
            qreg[h][0] = qs[ii * DIN + h * 64 + lane];
            qreg[h][1] = qs[ii * DIN + h * 64 + lane + 32];
        }
    }

    // =================== PASS 1: sim + edge bias ===================
    for (int jt = 0; jt < NN; jt += JTILE) {
        {
            const float4* src = (const float4*)&g_k[(b * NN + jt) * DIN];
            float4* dst = (float4*)kvs;
            #pragma unroll
            for (int l = 0; l < 8; l++) dst[t + l * 256] = src[t + l * 256];
        }
        for (int idx = t; idx < ITILE * JTILE * EDIM; idx += 256) {
            int r = idx / EDIM, a = idx - r * EDIM;
            int e_ii = r >> 5, jj = r & 31;
            esh[r * ESTRIDE + a] =
                edge_attr[((size_t)(b * NN + i0 + e_ii) * NN + jt + jj) * EDIM + a];
        }
        __syncthreads();

        for (int jj = 0; jj < JTILE; jj++) {
            const int j = jt + jj;
            if (!msh[ii * NN + j]) {
                if (lead) {
                    if (qch == 0) S[(ii * NH + hsel) * NN + j] = NEGMAX;
                    else          S2t[(qch - 1) * 256 + (ii * NH + hsel) * JTILE + jj] = 0.f;
                }
                continue;
            }
            const float* er = esh + (ii * JTILE + jj) * ESTRIDE;
            float4 ef0 = *(const float4*)er;
            float4 ef1 = *(const float4*)(er + 4);
            float4 ef2 = *(const float4*)(er + 8);
            float e[EDIM] = {ef0.x, ef0.y, ef0.z, ef0.w, ef1.x, ef1.y, ef1.z, ef1.w,
                             ef2.x, ef2.y, ef2.z};

            u64 red01, red23;
            if (qch == 0) {
                const float* kr = kvs + jj * DIN;
                float r0 = SCALE_F * (qreg[0][0] * kr[lane] + qreg[0][1] * kr[lane + 32]);
                float r1 = SCALE_F * (qreg[1][0] * kr[64 + lane] + qreg[1][1] * kr[96 + lane]);
                float r2 = SCALE_F * (qreg[2][0] * kr[128 + lane] + qreg[2][1] * kr[160 + lane]);
                float r3 = SCALE_F * (qreg[3][0] * kr[192 + lane] + qreg[3][1] * kr[224 + lane]);
                red01 = pack2(r0, r1);
                red23 = pack2(r2, r3);
            } else {
                red01 = 0ull;
                red23 = 0ull;
            }

            u64 s2 = b1p;
            #pragma unroll
            for (int a = 0; a < EDIM; a++) {
                u64 ea = pack2(e[a], e[a]);
                s2 = fma2(ea, W1p[a], s2);
            }
            float sA, sB;
            unpack2(s2, sA, sB);
            u64 gA = pack2(gelu_fast(sA), gelu_fast(sA));
            u64 gB = pack2(gelu_fast(sB), gelu_fast(sB));
            red01 = fma2(gA, W2p[0][0], red01);  red23 = fma2(gA, W2p[0][1], red23);
            red01 = fma2(gB, W2p[1][0], red01);  red23 = fma2(gB, W2p[1][1], red23);
            float red0, red1, red2, red3;
            unpack2(red01, red0, red1);
            unpack2(red23, red2, red3);

            #pragma unroll
            for (int off = 16; off >= 8; off >>= 1) {
                red0 += __shfl_xor_sync(0xffffffffu, red0, off);
                red1 += __shfl_xor_sync(0xffffffffu, red1, off);
                red2 += __shfl_xor_sync(0xffffffffu, red2, off);
                red3 += __shfl_xor_sync(0xffffffffu, red3, off);
            }
            float w = (hsel == 0) ? red0 : (hsel == 1) ? red1 : (hsel == 2) ? red2 : red3;
            w += __shfl_xor_sync(0xffffffffu, w, 4);
            w += __shfl_xor_sync(0xffffffffu, w, 2);
            w += __shfl_xor_sync(0xffffffffu, w, 1);
            if (lead) {
                if (qch == 0) S[(ii * NH + hsel) * NN + j] = w + b2h;
                else          S2t[(qch - 1) * 256 + (ii * NH + hsel) * JTILE + jj] = w;
            }
        }
        __syncthreads();
        // combine the 3 quarter-partials into S (one entry per thread)
        {
            int r = t >> 5, jj = t & 31;
            S[r * NN + jt + jj] += S2t[t] + S2t[256 + t] + S2t[512 + t];
        }
        __syncthreads();
    }

    // =================== PASS 2: softmax (8 warps x 1 row) ===================
    {
        const int row = warp;                // 0..7 == rii*4 + h
        const int rii = row >> 2, h = row & 3;
        float vals[16];
        float m = NEGMAX;
        #pragma unroll
        for (int kk = 0; kk < 16; kk++) {
            vals[kk] = S[row * NN + lane + kk * 32];
            m = fmaxf(m, vals[kk]);
        }
        #pragma unroll
        for (int off = 16; off > 0; off >>= 1)
            m = fmaxf(m, __shfl_xor_sync(0xffffffffu, m, off));
        float sum = 0.f;
        #pragma unroll
        for (int kk = 0; kk < 16; kk++) {
            float p = __expf(vals[kk] - m);
            vals[kk] = p;
            sum += p;
        }
        #pragma unroll
        for (int off = 16; off > 0; off >>= 1)
            sum += __shfl_xor_sync(0xffffffffu, sum, off);
        const float inv = 1.0f / sum;
        float* arow = attn_out + (((size_t)b * NH + h) * NN + (i0 + rii)) * NN;
        #pragma unroll
        for (int kk = 0; kk < 16; kk++) {
            float a = vals[kk] * inv;
            S[row * NN + lane + kk * 32] = a;
            arow[lane + kk * 32] = a;
        }
    }
    __syncthreads();

    // =================== PASS 3: t and attn@v accumulation ===================
    {
        int cc0 = qch * 64 + lane;
        int cc1 = cc0 + 32;
        b1p = pack2(bev1[cc0], bev1[cc1]);
        #pragma unroll
        for (int a = 0; a < EDIM; a++)
            W1p[a] = pack2(Wev1[a * DIN + cc0], Wev1[a * DIN + cc1]);
    }
    u64 tr2[NH];
    #pragma unroll
    for (int h = 0; h < NH; h++) tr2[h] = 0ull;
    float va0 = 0.f, va1 = 0.f;   // head qch v-accumulation

    for (int jt = 0; jt < NN; jt += JTILE) {
        {
            const float4* src = (const float4*)&g_v[(b * NN + jt) * DIN];
            float4* dst = (float4*)kvs;
            #pragma unroll
            for (int l = 0; l < 8; l++) dst[t + l * 256] = src[t + l * 256];
        }
        for (int idx = t; idx < ITILE * JTILE * EDIM; idx += 256) {
            int r = idx / EDIM, a = idx - r * EDIM;
            int e_ii = r >> 5, jj = r & 31;
            esh[r * ESTRIDE + a] =
                edge_attr[((size_t)(b * NN + i0 + e_ii) * NN + jt + jj) * EDIM + a];
        }
        __syncthreads();

        for (int jj = 0; jj < JTILE; jj++) {
            const int j = jt + jj;
            if (!msh[ii * NN + j]) continue;

            const float* er = esh + (ii * JTILE + jj) * ESTRIDE;
            float4 ef0 = *(const float4*)er;
            float4 ef1 = *(const float4*)(er + 4);
            float4 ef2 = *(const float4*)(er + 8);
            float e[EDIM] = {ef0.x, ef0.y, ef0.z, ef0.w, ef1.x, ef1.y, ef1.z, ef1.w,
                             ef2.x, ef2.y, ef2.z};

            u64 s2 = b1p;
            #pragma unroll
            for (int a = 0; a < EDIM; a++) {
                u64 ea = pack2(e[a], e[a]);
                s2 = fma2(ea, W1p[a], s2);
            }
            float sA, sB;
            unpack2(s2, sA, sB);
            u64 g2 = pack2(gelu_fast(sA), gelu_fast(sB));
            #pragma unroll
            for (int h = 0; h < NH; h++) {
                float ah = S[(ii * NH + h) * NN + j];
                tr2[h] = fma2(pack2(ah, ah), g2, tr2[h]);
            }
            const float* vr = kvs + jj * DIN;
            float aq = S[(ii * NH + qch) * NN + j];
            va0 += aq * vr[qch * 64 + lane];
            va1 += aq * vr[qch * 64 + lane + 32];
        }
        __syncthreads();
    }

    // dump accumulators
    #pragma unroll
    for (int h = 0; h < NH; h++) {
        float tA, tB;
        unpack2(tr2[h], tA, tB);
        float* trow = &tsh[(ii * NH + h) * DIN + qch * 64 + lane];
        trow[0]  = tA;
        trow[32] = tB;
    }
    vacc[ii * DIN + qch * 64 + lane]      = va0;
    vacc[ii * DIN + qch * 64 + lane + 32] = va1;
    __syncthreads();

    // =================== FINAL: o_inner = vacc + t@Wev2 + bev2 ===================
    {
        const int col = t;
        const int h = col >> 6;
        const float bcol = bev2[col];
        #pragma unroll
        for (int i2 = 0; i2 < ITILE; i2++) {
            const float* trow = &tsh[(i2 * NH + h) * DIN];
            float acc0 = 0.f, acc1 = 0.f, acc2 = 0.f, acc3 = 0.f;
            #pragma unroll 4
            for (int cc = 0; cc < DIN; cc += 4) {
                acc0 += trow[cc]     * Wev2[(cc)     * DIN + col];
                acc1 += trow[cc + 1] * Wev2[(cc + 1) * DIN + col];
                acc2 += trow[cc + 2] * Wev2[(cc + 2) * DIN + col];
                acc3 += trow[cc + 3] * Wev2[(cc + 3) * DIN + col];
            }
            g_oi[(b * NN + i0 + i2) * DIN + col] =
                ((acc0 + acc1) + (acc2 + acc3)) + vacc[i2 * DIN + col] + bcol;
        }
    }
}

// ============================================================
extern "C" void kernel_launch(void* const* d_in, const int* in_sizes, int n_in,
                              void* d_out, int out_size)
{
    const float* x           = (const float*)d_in[0];
    const void*  mask_raw    = d_in[1];
    const float* ea          = (const float*)d_in[2];
    const float* Wq          = (const float*)d_in[3];
    const float* Wk          = (const float*)d_in[4];
    const float* Wv          = (const float*)d_in[5];
    const float* Web1        = (const float*)d_in[6];
    const float* beb1        = (const float*)d_in[7];
    const float* Web2        = (const float*)d_in[8];
    const float* beb2        = (const float*)d_in[9];
    const float* Wev1        = (const float*)d_in[10];
    const float* bev1        = (const float*)d_in[11];
    const float* Wev2        = (const float*)d_in[12];
    const float* bev2        = (const float*)d_in[13];
    const float* Wo          = (const float*)d_in[14];
    const float* bo          = (const float*)d_in[15];

    float* out = (float*)d_out;
    const int out_elems  = BB * NN * QDIM;              // 524288
    const int attn_elems = BB * NH * NN * NN;           // 2097152
    const int mask_elems = BB * NN * NN;                // 524288

    float *oip, *attn_fb;
    unsigned char* maskp;
    cudaGetSymbolAddress((void**)&oip, g_oi);
    cudaGetSymbolAddress((void**)&attn_fb, g_attn_scratch);
    cudaGetSymbolAddress((void**)&maskp, g_mask);

    float* attn = (out_size >= out_elems + attn_elems) ? (out + out_elems) : attn_fb;

    const int smem_bytes = 16640 * 4;   // 66560
    cudaFuncSetAttribute(attn_fused, cudaFuncAttributeMaxDynamicSharedMemorySize, smem_bytes);

    // mask canonicalize (dtype detection embedded)
    canon_mask_kernel<<<256, 256>>>((const unsigned int*)mask_raw, mask_elems);

    // fused q/k/v projections: 3 x 8 x 16 = 384 blocks
    qkv_gemm<<<dim3(24, (BB * NN) / 64), 256>>>(x, Wq, Wk, Wv);

    // fused attention + edge MLPs (256 thr, 3 blocks/SM target, 512 blocks)
    attn_fused<<<dim3(NN / ITILE, BB), 256, smem_bytes>>>(
        ea, maskp, Web1, beb1, Web2, beb2, Wev1, bev1, Wev2, bev2, attn);

    // final projection: out = o_inner @ Wo + bo
    gemm_tiled<<<dim3(QDIM / 32, (BB * NN) / 64), 256>>>(oip, Wo, bo, out, BB * NN, DIN, QDIM);
}

// round 13
// speedup vs baseline: 1.3620x; 1.3620x over previous
#include <cuda_runtime.h>
#include <math.h>

#define BB 2
#define NN 512
#define QDIM 512
#define EDIM 11
#define NH 4
#define DHEAD 64
#define DIN 256          // INNER = NH*DHEAD
#define SCALE_F 0.125f   // 64^-0.5
#define NEGMAX -3.402823466e38f

#define ITILE 4
#define JTILE 32
#define ESTRIDE 12       // padded edge-feature row stride

// -------- device scratch (no allocations allowed) --------
__device__ float g_q[BB * NN * DIN];
__device__ float g_k[BB * NN * DIN];
__device__ float g_v[BB * NN * DIN];
__device__ float g_oi[BB * NN * DIN];
__device__ float g_attn_scratch[BB * NH * NN * NN];

typedef unsigned long long u64;

// ---- packed fp32x2 helpers ----
__device__ __forceinline__ u64 pack2(float lo, float hi) {
    u64 r; asm("mov.b64 %0, {%1, %2};" : "=l"(r) : "f"(lo), "f"(hi)); return r;
}
__device__ __forceinline__ void unpack2(u64 v, float& lo, float& hi) {
    asm("mov.b64 {%0, %1}, %2;" : "=f"(lo), "=f"(hi) : "l"(v));
}
__device__ __forceinline__ u64 fma2(u64 a, u64 b, u64 c) {
    u64 d; asm("fma.rn.f32x2 %0, %1, %2, %3;" : "=l"(d) : "l"(a), "l"(b), "l"(c)); return d;
}

// lean fast GELU (validated: total rel_err ~5e-7)
__device__ __forceinline__ float gelu_fast(float x) {
    float x2 = x * x;
    float u = x * fmaf(0.0356774081f, x2, 0.7978845608f);
    float th;
    asm("tanh.approx.f32 %0, %1;" : "=f"(th) : "f"(u));
    float hx = 0.5f * x;
    return fmaf(hx, th, hx);
}

// ============================================================
// GEMM 64x32 tile, 256 threads, 4x2 per thread, K-tile 16.
// ============================================================
__device__ __forceinline__ void gemm_body(
    const float* __restrict__ A, const float* __restrict__ W,
    const float* __restrict__ bias, float* __restrict__ C,
    int M, int K, int Nc, int m0, int n0)
{
    __shared__ float As[16][65];
    __shared__ float Bs[16][33];
    const int t = threadIdx.x;
    const int r = t >> 4, c = t & 15;
    float acc[4][2] = {};

    for (int k0 = 0; k0 < K; k0 += 16) {
        #pragma unroll
        for (int l = 0; l < 4; l++) {
            int idx = t + l * 256;
            int mm = idx >> 4, kk = idx & 15;
            As[kk][mm] = A[(m0 + mm) * K + (k0 + kk)];
        }
        #pragma unroll
        for (int l = 0; l < 2; l++) {
            int idx = t + l * 256;
            int kk = idx >> 5, nn = idx & 31;
            Bs[kk][nn] = W[(k0 + kk) * Nc + (n0 + nn)];
        }
        __syncthreads();
        #pragma unroll
        for (int kk = 0; kk < 16; kk++) {
            float av[4], bv[2];
            #pragma unroll
            for (int l = 0; l < 4; l++) av[l] = As[kk][r * 4 + l];
            bv[0] = Bs[kk][c * 2];
            bv[1] = Bs[kk][c * 2 + 1];
            #pragma unroll
            for (int i = 0; i < 4; i++) {
                acc[i][0] += av[i] * bv[0];
                acc[i][1] += av[i] * bv[1];
            }
        }
        __syncthreads();
    }

    #pragma unroll
    for (int i = 0; i < 4; i++)
        #pragma unroll
        for (int j = 0; j < 2; j++) {
            int m = m0 + r * 4 + i, n = n0 + c * 2 + j;
            float v = acc[i][j];
            if (bias) v += bias[n];
            C[m * Nc + n] = v;
        }
}

__global__ __launch_bounds__(256) void qkv_gemm(
    const float* __restrict__ x,
    const float* __restrict__ Wq, const float* __restrict__ Wk, const float* __restrict__ Wv)
{
    const int sel = blockIdx.x >> 3;
    const int n0 = (blockIdx.x & 7) * 32;
    const int m0 = blockIdx.y * 64;
    const float* W = (sel == 0) ? Wq : (sel == 1) ? Wk : Wv;
    float* C = (sel == 0) ? g_q : (sel == 1) ? g_k : g_v;
    gemm_body(x, W, nullptr, C, BB * NN, QDIM, DIN, m0, n0);
}

__global__ __launch_bounds__(256) void gemm_tiled(
    const float* __restrict__ A, const float* __restrict__ W,
    const float* __restrict__ bias, float* __restrict__ C,
    int M, int K, int Nc)
{
    gemm_body(A, W, bias, C, M, K, Nc, blockIdx.y * 64, blockIdx.x * 32);
}

// ============================================================
// Fused attention (R10 hot loops, byte-identical).
// Mask dtype detection + conversion fused into the prologue;
// attn global store made conditional + vectorized.
// block = (b, 4 query rows), 256 threads, 2 blocks/SM.
// ============================================================
__global__ __launch_bounds__(256, 2) void attn_fused(
    const float* __restrict__ edge_attr,
    const unsigned int* __restrict__ mask_raw,
    const float* __restrict__ Web1, const float* __restrict__ beb1,
    const float* __restrict__ Web2, const float* __restrict__ beb2,
    const float* __restrict__ Wev1, const float* __restrict__ bev1,
    const float* __restrict__ Wev2, const float* __restrict__ bev2,
    float* __restrict__ attn_out, int store_attn)
{
    extern __shared__ float sm[];
    float* qs   = sm;                  // 1024
    float* S    = sm + 1024;           // 8192
    float* tsh  = sm + 9216;           // 4096
    float* vacc = sm + 13312;          // 1024
    float* esh  = sm + 14336;          // 1536
    float* kvs  = sm + 15872;          // 8192
    float* S2t  = sm + 24064;          // 512
    unsigned char* msh = (unsigned char*)(sm + 24576);  // 2048 B
    // total 25088 floats = 100352 bytes

    const int t = threadIdx.x;
    const int warp = t >> 5, lane = t & 31;
    const int b = blockIdx.y;
    const int i0 = blockIdx.x * ITILE;
    const int ii = warp >> 1;
    const int ch = warp & 1;

    // ---- stage q rows ----
    ((float4*)qs)[t] = ((const float4*)&g_q[(b * NN + i0) * DIN])[t];

    // ---- mask dtype detection (deterministic, same data every block) ----
    {
        unsigned int v0 = mask_raw[t];
        unsigned int v1 = mask_raw[t + 256];
        int weird = (v0 > 1u && v0 != 0x3F800000u) || (v1 > 1u && v1 != 0x3F800000u);
        int flt   = (v0 == 0x3F800000u) || (v1 == 0x3F800000u);
        weird = __syncthreads_or(weird);
        flt   = __syncthreads_or(flt);
        const int mode = weird ? 2 : (flt ? 1 : 0);

        // convert this block's 4 rows (2048 elements) into msh bytes
        const int base = (b * NN + i0) * NN;   // element offset, multiple of 2048
        if (mode == 2) {
            // byte storage: copy 2048 bytes = 512 words
            ((unsigned int*)msh)[t]       = mask_raw[(base >> 2) + t];
            ((unsigned int*)msh)[t + 256] = mask_raw[(base >> 2) + t + 256];
        } else if (mode == 1) {
            const float* mf = (const float*)mask_raw + base;
            #pragma unroll
            for (int l = 0; l < 8; l++)
                msh[t + l * 256] = (mf[t + l * 256] != 0.0f);
        } else {
            const unsigned int* mi = mask_raw + base;
            #pragma unroll
            for (int l = 0; l < 8; l++)
                msh[t + l * 256] = (mi[t + l * 256] != 0u);
        }
    }

    // ---- per-lane packed weights (bias MLP) ----
    u64 W1p[EDIM][2], b1p[2], W2p[4][2];
    #pragma unroll
    for (int p = 0; p < 2; p++) {
        int cc0 = ch * 128 + lane + 64 * p;
        int cc1 = cc0 + 32;
        b1p[p] = pack2(beb1[cc0], beb1[cc1]);
        #pragma unroll
        for (int a = 0; a < EDIM; a++)
            W1p[a][p] = pack2(Web1[a * DIN + cc0], Web1[a * DIN + cc1]);
    }
    #pragma unroll
    for (int idx4 = 0; idx4 < 4; idx4++) {
        int p = idx4 >> 1, hi = idx4 & 1;
        int cc = ch * 128 + lane + 64 * p + 32 * hi;
        W2p[idx4][0] = pack2(Web2[cc * NH + 0], Web2[cc * NH + 1]);
        W2p[idx4][1] = pack2(Web2[cc * NH + 2], Web2[cc * NH + 3]);
    }
    const float b20 = beb2[0], b21 = beb2[1], b22 = beb2[2], b23 = beb2[3];
    __syncthreads();

    // hoist this row's q into registers (ch==0 warps compute qk)
    float qreg[NH][2];
    if (ch == 0) {
        #pragma unroll
        for (int h = 0; h < NH; h++) {
            qreg[h][0] = qs[ii * DIN + h * 64 + lane];
            qreg[h][1] = qs[ii * DIN + h * 64 + lane + 32];
        }
    }

    // =================== PASS 1: sim + edge bias (R10) ===================
    for (int jt = 0; jt < NN; jt += JTILE) {
        {
            const float4* src = (const float4*)&g_k[(b * NN + jt) * DIN];
            float4* dst = (float4*)kvs;
            #pragma unroll
            for (int l = 0; l < 8; l++) dst[t + l * 256] = src[t + l * 256];
        }
        for (int idx = t; idx < ITILE * JTILE * EDIM; idx += 256) {
            int r = idx / EDIM, a = idx - r * EDIM;
            int e_ii = r >> 5, jj = r & 31;
            esh[r * ESTRIDE + a] =
                edge_attr[((size_t)(b * NN + i0 + e_ii) * NN + jt + jj) * EDIM + a];
        }
        __syncthreads();

        int pj = -1;
        u64 p01 = 0ull, p23 = 0ull;
        const int hsel = lane >> 3;
        const int lead = ((lane & 7) == 0);
        const float b2h = (hsel == 0) ? b20 : (hsel == 1) ? b21 : (hsel == 2) ? b22 : b23;

        for (int jj = 0; jj < JTILE; jj++) {
            const int j = jt + jj;
            if (!msh[ii * NN + j]) {
                if (lead) {
                    if (ch == 0) S[(ii * NH + hsel) * NN + j] = NEGMAX;
                    else         S2t[(ii * NH + hsel) * JTILE + jj] = 0.f;
                }
                continue;
            }
            const float* er = esh + (ii * JTILE + jj) * ESTRIDE;
            float4 ef0 = *(const float4*)er;
            float4 ef1 = *(const float4*)(er + 4);
            float4 ef2 = *(const float4*)(er + 8);
            float e[EDIM] = {ef0.x, ef0.y, ef0.z, ef0.w, ef1.x, ef1.y, ef1.z, ef1.w,
                             ef2.x, ef2.y, ef2.z};

            u64 red01, red23;
            if (ch == 0) {
                const float* kr = kvs + jj * DIN;
                float r0 = SCALE_F * (qreg[0][0] * kr[lane] + qreg[0][1] * kr[lane + 32]);
                float r1 = SCALE_F * (qreg[1][0] * kr[64 + lane] + qreg[1][1] * kr[96 + lane]);
                float r2 = SCALE_F * (qreg[2][0] * kr[128 + lane] + qreg[2][1] * kr[160 + lane]);
                float r3 = SCALE_F * (qreg[3][0] * kr[192 + lane] + qreg[3][1] * kr[224 + lane]);
                red01 = pack2(r0, r1);
                red23 = pack2(r2, r3);
            } else {
                red01 = 0ull;
                red23 = 0ull;
            }

            u64 s2a = b1p[0], s2b = b1p[1];
            #pragma unroll
            for (int a = 0; a < EDIM; a++) {
                u64 ea = pack2(e[a], e[a]);
                s2a = fma2(ea, W1p[a][0], s2a);
                s2b = fma2(ea, W1p[a][1], s2b);
            }
            float sA, sB, sC, sD;
            unpack2(s2a, sA, sB);
            unpack2(s2b, sC, sD);
            u64 gA = pack2(gelu_fast(sA), gelu_fast(sA));
            u64 gB = pack2(gelu_fast(sB), gelu_fast(sB));
            u64 gC = pack2(gelu_fast(sC), gelu_fast(sC));
            u64 gD = pack2(gelu_fast(sD), gelu_fast(sD));
            red01 = fma2(gA, W2p[0][0], red01);  red23 = fma2(gA, W2p[0][1], red23);
            red01 = fma2(gB, W2p[1][0], red01);  red23 = fma2(gB, W2p[1][1], red23);
            red01 = fma2(gC, W2p[2][0], red01);  red23 = fma2(gC, W2p[2][1], red23);
            red01 = fma2(gD, W2p[3][0], red01);  red23 = fma2(gD, W2p[3][1], red23);

            if (pj < 0) { pj = j; p01 = red01; p23 = red23; continue; }

            float a0, a1, a2, a3, c0, c1, c2, c3;
            unpack2(p01, a0, a1); unpack2(p23, a2, a3);
            unpack2(red01, c0, c1); unpack2(red23, c2, c3);
            #pragma unroll
            for (int off = 16; off >= 8; off >>= 1) {
                a0 += __shfl_xor_sync(0xffffffffu, a0, off);
                c0 += __shfl_xor_sync(0xffffffffu, c0, off);
                a1 += __shfl_xor_sync(0xffffffffu, a1, off);
                c1 += __shfl_xor_sync(0xffffffffu, c1, off);
                a2 += __shfl_xor_sync(0xffffffffu, a2, off);
                c2 += __shfl_xor_sync(0xffffffffu, c2, off);
                a3 += __shfl_xor_sync(0xffffffffu, a3, off);
                c3 += __shfl_xor_sync(0xffffffffu, c3, off);
            }
            float wA = (hsel == 0) ? a0 : (hsel == 1) ? a1 : (hsel == 2) ? a2 : a3;
            float wB = (hsel == 0) ? c0 : (hsel == 1) ? c1 : (hsel == 2) ? c2 : c3;
            #pragma unroll
            for (int off = 4; off > 0; off >>= 1) {
                wA += __shfl_xor_sync(0xffffffffu, wA, off);
                wB += __shfl_xor_sync(0xffffffffu, wB, off);
            }
            if (lead) {
                if (ch == 0) {
                    S[(ii * NH + hsel) * NN + pj] = wA + b2h;
                    S[(ii * NH + hsel) * NN + j]  = wB + b2h;
                } else {
                    S2t[(ii * NH + hsel) * JTILE + (pj - jt)] = wA;
                    S2t[(ii * NH + hsel) * JTILE + jj]        = wB;
                }
            }
            pj = -1;
        }
        if (pj >= 0) {
            float a0, a1, a2, a3;
            unpack2(p01, a0, a1); unpack2(p23, a2, a3);
            #pragma unroll
            for (int off = 16; off >= 8; off >>= 1) {
                a0 += __shfl_xor_sync(0xffffffffu, a0, off);
                a1 += __shfl_xor_sync(0xffffffffu, a1, off);
                a2 += __shfl_xor_sync(0xffffffffu, a2, off);
                a3 += __shfl_xor_sync(0xffffffffu, a3, off);
            }
            float wA = (hsel == 0) ? a0 : (hsel == 1) ? a1 : (hsel == 2) ? a2 : a3;
            #pragma unroll
            for (int off = 4; off > 0; off >>= 1)
                wA += __shfl_xor_sync(0xffffffffu, wA, off);
            if (lead) {
                if (ch == 0) S[(ii * NH + hsel) * NN + pj] = wA + b2h;
                else         S2t[(ii * NH + hsel) * JTILE + (pj - jt)] = wA;
            }
        }
        __syncthreads();
        #pragma unroll
        for (int l = 0; l < 2; l++) {
            int idx = t + l * 256;
            int r = idx >> 5, jj = idx & 31;
            S[r * NN + jt + jj] += S2t[idx];
        }
        __syncthreads();
    }

    // =================== PASS 2: softmax (8 warps x 2 rows) ===================
    #pragma unroll
    for (int rr = 0; rr < 2; rr++) {
        const int row = warp * 2 + rr;
        float vals[16];
        float m = NEGMAX;
        #pragma unroll
        for (int kk = 0; kk < 16; kk++) {
            vals[kk] = S[row * NN + lane + kk * 32];
            m = fmaxf(m, vals[kk]);
        }
        #pragma unroll
        for (int off = 16; off > 0; off >>= 1)
            m = fmaxf(m, __shfl_xor_sync(0xffffffffu, m, off));
        float sum = 0.f;
        #pragma unroll
        for (int kk = 0; kk < 16; kk++) {
            float p = __expf(vals[kk] - m);
            vals[kk] = p;
            sum += p;
        }
        #pragma unroll
        for (int off = 16; off > 0; off >>= 1)
            sum += __shfl_xor_sync(0xffffffffu, sum, off);
        const float inv = 1.0f / sum;
        #pragma unroll
        for (int kk = 0; kk < 16; kk++)
            S[row * NN + lane + kk * 32] = vals[kk] * inv;
    }
    __syncthreads();

    // ---- vectorized attn store (only when the harness checks it) ----
    if (store_attn) {
        // S row layout (ii*NH+h)*NN matches attn rows (b,h,i0+ii)
        #pragma unroll
        for (int l = 0; l < 8; l++) {
            int idx = t + l * 256;           // float4 index within 16x512 tile
            int row = idx >> 7;              // 0..15 == ii*NH+h
            int col4 = idx & 127;
            int rii = row >> 2, h = row & 3;
            float4 v = ((const float4*)S)[idx];
            ((float4*)(attn_out + (((size_t)b * NH + h) * NN + (i0 + rii)) * NN))[col4] = v;
        }
    }
    __syncthreads();

    // =================== PASS 3: t and attn@v accumulation (R10 paired) ===================
    u64 W1p3[EDIM][2], b1p3[2];
    #pragma unroll
    for (int p = 0; p < 2; p++) {
        int cc0 = ch * 128 + lane + 64 * p;
        int cc1 = cc0 + 32;
        b1p3[p] = pack2(bev1[cc0], bev1[cc1]);
        #pragma unroll
        for (int a = 0; a < EDIM; a++)
            W1p3[a][p] = pack2(Wev1[a * DIN + cc0], Wev1[a * DIN + cc1]);
    }
    u64 tr2[NH][2];
    #pragma unroll
    for (int h = 0; h < NH; h++) { tr2[h][0] = 0ull; tr2[h][1] = 0ull; }
    float va[2][2] = {};

    for (int jt = 0; jt < NN; jt += JTILE) {
        {
            const float4* src = (const float4*)&g_v[(b * NN + jt) * DIN];
            float4* dst = (float4*)kvs;
            #pragma unroll
            for (int l = 0; l < 8; l++) dst[t + l * 256] = src[t + l * 256];
        }
        for (int idx = t; idx < ITILE * JTILE * EDIM; idx += 256) {
            int r = idx / EDIM, a = idx - r * EDIM;
            int e_ii = r >> 5, jj = r & 31;
            esh[r * ESTRIDE + a] =
                edge_attr[((size_t)(b * NN + i0 + e_ii) * NN + jt + jj) * EDIM + a];
        }
        __syncthreads();

        int pj = -1;
        u64 ps2a = 0ull, ps2b = 0ull;

        for (int jj = 0; jj < JTILE; jj++) {
            const int j = jt + jj;
            if (!msh[ii * NN + j]) continue;

            const float* er = esh + (ii * JTILE + jj) * ESTRIDE;
            float4 ef0 = *(const float4*)er;
            float4 ef1 = *(const float4*)(er + 4);
            float4 ef2 = *(const float4*)(er + 8);
            float e[EDIM] = {ef0.x, ef0.y, ef0.z, ef0.w, ef1.x, ef1.y, ef1.z, ef1.w,
                             ef2.x, ef2.y, ef2.z};

            u64 s2a = b1p3[0], s2b = b1p3[1];
            #pragma unroll
            for (int a = 0; a < EDIM; a++) {
                u64 ea = pack2(e[a], e[a]);
                s2a = fma2(ea, W1p3[a][0], s2a);
                s2b = fma2(ea, W1p3[a][1], s2b);
            }

            if (pj < 0) { pj = j; ps2a = s2a; ps2b = s2b; continue; }

            float xA, xB, xC, xD, yA, yB, yC, yD;
            unpack2(ps2a, xA, xB); unpack2(ps2b, xC, xD);
            unpack2(s2a, yA, yB);  unpack2(s2b, yC, yD);
            u64 gA2a = pack2(gelu_fast(xA), gelu_fast(xB));
            u64 gA2b = pack2(gelu_fast(xC), gelu_fast(xD));
            u64 gB2a = pack2(gelu_fast(yA), gelu_fast(yB));
            u64 gB2b = pack2(gelu_fast(yC), gelu_fast(yD));

            #pragma unroll
            for (int h = 0; h < NH; h++) {
                float aAh = S[(ii * NH + h) * NN + pj];
                float aBh = S[(ii * NH + h) * NN + j];
                u64 pA = pack2(aAh, aAh);
                u64 pB = pack2(aBh, aBh);
                tr2[h][0] = fma2(pA, gA2a, tr2[h][0]);
                tr2[h][1] = fma2(pA, gA2b, tr2[h][1]);
                tr2[h][0] = fma2(pB, gB2a, tr2[h][0]);
                tr2[h][1] = fma2(pB, gB2b, tr2[h][1]);
            }
            {
                const float* vrA = kvs + (pj - jt) * DIN;
                const float* vrB = kvs + jj * DIN;
                #pragma unroll
                for (int hh = 0; hh < 2; hh++) {
                    const int h = ch * 2 + hh;
                    float aAh = S[(ii * NH + h) * NN + pj];
                    float aBh = S[(ii * NH + h) * NN + j];
                    va[hh][0] += aAh * vrA[h * 64 + lane] + aBh * vrB[h * 64 + lane];
                    va[hh][1] += aAh * vrA[h * 64 + lane + 32] + aBh * vrB[h * 64 + lane + 32];
                }
            }
            pj = -1;
        }
        if (pj >= 0) {
            float xA, xB, xC, xD;
            unpack2(ps2a, xA, xB); unpack2(ps2b, xC, xD);
            u64 gA2a = pack2(gelu_fast(xA), gelu_fast(xB));
            u64 gA2b = pack2(gelu_fast(xC), gelu_fast(xD));
            #pragma unroll
            for (int h = 0; h < NH; h++) {
                float aAh = S[(ii * NH + h) * NN + pj];
                u64 pA = pack2(aAh, aAh);
                tr2[h][0] = fma2(pA, gA2a, tr2[h][0]);
                tr2[h][1] = fma2(pA, gA2b, tr2[h][1]);
            }
            const float* vrA = kvs + (pj - jt) * DIN;
            #pragma unroll
            for (int hh = 0; hh < 2; hh++) {
                const int h = ch * 2 + hh;
                float aAh = S[(ii * NH + h) * NN + pj];
                va[hh][0] += aAh * vrA[h * 64 + lane];
                va[hh][1] += aAh * vrA[h * 64 + lane + 32];
            }
        }
        __syncthreads();
    }

    // dump accumulators (chain order: p0_lo, p0_hi, p1_lo, p1_hi)
    #pragma unroll
    for (int h = 0; h < NH; h++) {
        float tA, tB, tC, tD;
        unpack2(tr2[h][0], tA, tB);
        unpack2(tr2[h][1], tC, tD);
        float* trow = &tsh[(ii * NH + h) * DIN + ch * 128 + lane];
        trow[0]  = tA;
        trow[32] = tB;
        trow[64] = tC;
        trow[96] = tD;
    }
    #pragma unroll
    for (int hh = 0; hh < 2; hh++) {
        const int h = ch * 2 + hh;
        vacc[ii * DIN + h * 64 + lane]      = va[hh][0];
        vacc[ii * DIN + h * 64 + lane + 32] = va[hh][1];
    }
    __syncthreads();

    // =================== FINAL: o_inner = vacc + t@Wev2 + bev2 ===================
    {
        const int col = t;
        const int h = col >> 6;
        const float bcol = bev2[col];
        #pragma unroll
        for (int i2 = 0; i2 < ITILE; i2++) {
            const float* trow = &tsh[(i2 * NH + h) * DIN];
            float acc0 = 0.f, acc1 = 0.f, acc2 = 0.f, acc3 = 0.f;
            #pragma unroll 4
            for (int cc = 0; cc < DIN; cc += 4) {
                acc0 += trow[cc]     * Wev2[(cc)     * DIN + col];
                acc1 += trow[cc + 1] * Wev2[(cc + 1) * DIN + col];
                acc2 += trow[cc + 2] * Wev2[(cc + 2) * DIN + col];
                acc3 += trow[cc + 3] * Wev2[(cc + 3) * DIN + col];
            }
            g_oi[(b * NN + i0 + i2) * DIN + col] =
                ((acc0 + acc1) + (acc2 + acc3)) + vacc[i2 * DIN + col] + bcol;
        }
    }
}

// ============================================================
extern "C" void kernel_launch(void* const* d_in, const int* in_sizes, int n_in,
                              void* d_out, int out_size)
{
    const float* x           = (const float*)d_in[0];
    const void*  mask_raw    = d_in[1];
    const float* ea          = (const float*)d_in[2];
    const float* Wq          = (const float*)d_in[3];
    const float* Wk          = (const float*)d_in[4];
    const float* Wv          = (const float*)d_in[5];
    const float* Web1        = (const float*)d_in[6];
    const float* beb1        = (const float*)d_in[7];
    const float* Web2        = (const float*)d_in[8];
    const float* beb2        = (const float*)d_in[9];
    const float* Wev1        = (const float*)d_in[10];
    const float* bev1        = (const float*)d_in[11];
    const float* Wev2        = (const float*)d_in[12];
    const float* bev2        = (const float*)d_in[13];
    const float* Wo          = (const float*)d_in[14];
    const float* bo          = (const float*)d_in[15];

    float* out = (float*)d_out;
    const int out_elems  = BB * NN * QDIM;              // 524288
    const int attn_elems = BB * NH * NN * NN;           // 2097152

    float *oip, *attn_fb;
    cudaGetSymbolAddress((void**)&oip, g_oi);
    cudaGetSymbolAddress((void**)&attn_fb, g_attn_scratch);

    const int store_attn = (out_size >= out_elems + attn_elems) ? 1 : 0;
    float* attn = store_attn ? (out + out_elems) : attn_fb;

    const int smem_bytes = 25088 * 4;   // 100352
    cudaFuncSetAttribute(attn_fused, cudaFuncAttributeMaxDynamicSharedMemorySize, smem_bytes);

    // fused q/k/v projections: 3 x 8 x 16 = 384 blocks
    qkv_gemm<<<dim3(24, (BB * NN) / 64), 256>>>(x, Wq, Wk, Wv);

    // fused attention + edge MLPs (mask handling inlined; 256 thr, 2 blocks/SM)
    attn_fused<<<dim3(NN / ITILE, BB), 256, smem_bytes>>>(
        ea, (const unsigned int*)mask_raw, Web1, beb1, Web2, beb2,
        Wev1, bev1, Wev2, bev2, attn, store_attn);

    // final projection: out = o_inner @ Wo + bo
    gemm_tiled<<<dim3(QDIM / 32, (BB * NN) / 64), 256>>>(oip, Wo, bo, out, BB * NN, DIN, QDIM);
}

// round 14
// speedup vs baseline: 1.3854x; 1.0172x over previous
#include <cuda_runtime.h>
#include <math.h>

#define BB 2
#define NN 512
#define QDIM 512
#define EDIM 11
#define NH 4
#define DHEAD 64
#define DIN 256          // INNER = NH*DHEAD
#define SCALE_F 0.125f   // 64^-0.5
#define NEGMAX -3.402823466e38f

#define ITILE 4
#define JTILE 32
#define ESTRIDE 12       // padded edge-feature row stride

// -------- device scratch (no allocations allowed) --------
__device__ float g_q[BB * NN * DIN];
__device__ float g_k[BB * NN * DIN];
__device__ float g_v[BB * NN * DIN];
__device__ float g_oi[BB * NN * DIN];
__device__ float g_attn_scratch[BB * NH * NN * NN];

typedef unsigned long long u64;

// ---- packed fp32x2 helpers ----
__device__ __forceinline__ u64 pack2(float lo, float hi) {
    u64 r; asm("mov.b64 %0, {%1, %2};" : "=l"(r) : "f"(lo), "f"(hi)); return r;
}
__device__ __forceinline__ void unpack2(u64 v, float& lo, float& hi) {
    asm("mov.b64 {%0, %1}, %2;" : "=f"(lo), "=f"(hi) : "l"(v));
}
__device__ __forceinline__ u64 fma2(u64 a, u64 b, u64 c) {
    u64 d; asm("fma.rn.f32x2 %0, %1, %2, %3;" : "=l"(d) : "l"(a), "l"(b), "l"(c)); return d;
}

// lean fast GELU (validated: total rel_err ~5e-7)
__device__ __forceinline__ float gelu_fast(float x) {
    float x2 = x * x;
    float u = x * fmaf(0.0356774081f, x2, 0.7978845608f);
    float th;
    asm("tanh.approx.f32 %0, %1;" : "=f"(th) : "f"(u));
    float hx = 0.5f * x;
    return fmaf(hx, th, hx);
}

// ============================================================
// GEMM 64x64 tile, 256 threads, 4x4 per thread, K-tile 16.
// Vectorized: inner step = 2x LDS.128 + 16 FFMA per thread.
// Rows padded to 68 floats so [kk][r*4] is 16B-aligned.
// ============================================================
__device__ __forceinline__ void gemm_body(
    const float* __restrict__ A, const float* __restrict__ W,
    const float* __restrict__ bias, float* __restrict__ C,
    int M, int K, int Nc, int m0, int n0)
{
    __shared__ float As[16][68];
    __shared__ float Bs[16][68];
    const int t = threadIdx.x;
    const int r = t >> 4, c = t & 15;
    float acc[4][4] = {};

    for (int k0 = 0; k0 < K; k0 += 16) {
        // A tile: 64 rows x 16 k; each thread loads float4 along k, transposes into As
        {
            int mm = t >> 2, kk4 = (t & 3) * 4;
            float4 va4 = *(const float4*)&A[(m0 + mm) * K + k0 + kk4];
            As[kk4 + 0][mm] = va4.x;
            As[kk4 + 1][mm] = va4.y;
            As[kk4 + 2][mm] = va4.z;
            As[kk4 + 3][mm] = va4.w;
        }
        // B tile: 16 k x 64 n; float4 along n, STS.128
        {
            int kk = t >> 4, nn4 = (t & 15) * 4;
            *(float4*)&Bs[kk][nn4] = *(const float4*)&W[(k0 + kk) * Nc + n0 + nn4];
        }
        __syncthreads();
        #pragma unroll
        for (int kk = 0; kk < 16; kk++) {
            float4 av = *(const float4*)&As[kk][r * 4];
            float4 bv = *(const float4*)&Bs[kk][c * 4];
            acc[0][0] = fmaf(av.x, bv.x, acc[0][0]);
            acc[0][1] = fmaf(av.x, bv.y, acc[0][1]);
            acc[0][2] = fmaf(av.x, bv.z, acc[0][2]);
            acc[0][3] = fmaf(av.x, bv.w, acc[0][3]);
            acc[1][0] = fmaf(av.y, bv.x, acc[1][0]);
            acc[1][1] = fmaf(av.y, bv.y, acc[1][1]);
            acc[1][2] = fmaf(av.y, bv.z, acc[1][2]);
            acc[1][3] = fmaf(av.y, bv.w, acc[1][3]);
            acc[2][0] = fmaf(av.z, bv.x, acc[2][0]);
            acc[2][1] = fmaf(av.z, bv.y, acc[2][1]);
            acc[2][2] = fmaf(av.z, bv.z, acc[2][2]);
            acc[2][3] = fmaf(av.z, bv.w, acc[2][3]);
            acc[3][0] = fmaf(av.w, bv.x, acc[3][0]);
            acc[3][1] = fmaf(av.w, bv.y, acc[3][1]);
            acc[3][2] = fmaf(av.w, bv.z, acc[3][2]);
            acc[3][3] = fmaf(av.w, bv.w, acc[3][3]);
        }
        __syncthreads();
    }

    #pragma unroll
    for (int i = 0; i < 4; i++) {
        int m = m0 + r * 4 + i, n = n0 + c * 4;
        float4 v = make_float4(acc[i][0], acc[i][1], acc[i][2], acc[i][3]);
        if (bias) {
            v.x += bias[n];
            v.y += bias[n + 1];
            v.z += bias[n + 2];
            v.w += bias[n + 3];
        }
        *(float4*)&C[m * Nc + n] = v;
    }
}

// fused q/k/v projection: blockIdx.x = sel*4 + ntile (DIN/64 = 4 n-tiles)
__global__ __launch_bounds__(256) void qkv_gemm(
    const float* __restrict__ x,
    const float* __restrict__ Wq, const float* __restrict__ Wk, const float* __restrict__ Wv)
{
    const int sel = blockIdx.x >> 2;
    const int n0 = (blockIdx.x & 3) * 64;
    const int m0 = blockIdx.y * 64;
    const float* W = (sel == 0) ? Wq : (sel == 1) ? Wk : Wv;
    float* C = (sel == 0) ? g_q : (sel == 1) ? g_k : g_v;
    gemm_body(x, W, nullptr, C, BB * NN, QDIM, DIN, m0, n0);
}

__global__ __launch_bounds__(256) void gemm_tiled(
    const float* __restrict__ A, const float* __restrict__ W,
    const float* __restrict__ bias, float* __restrict__ C,
    int M, int K, int Nc)
{
    gemm_body(A, W, bias, C, M, K, Nc, blockIdx.y * 64, blockIdx.x * 64);
}

// ============================================================
// Fused attention (R13, byte-identical hot loops).
// block = (b, 4 query rows), 256 threads, 2 blocks/SM.
// ============================================================
__global__ __launch_bounds__(256, 2) void attn_fused(
    const float* __restrict__ edge_attr,
    const unsigned int* __restrict__ mask_raw,
    const float* __restrict__ Web1, const float* __restrict__ beb1,
    const float* __restrict__ Web2, const float* __restrict__ beb2,
    const float* __restrict__ Wev1, const float* __restrict__ bev1,
    const float* __restrict__ Wev2, const float* __restrict__ bev2,
    float* __restrict__ attn_out, int store_attn)
{
    extern __shared__ float sm[];
    float* qs   = sm;                  // 1024
    float* S    = sm + 1024;           // 8192
    float* tsh  = sm + 9216;           // 4096
    float* vacc = sm + 13312;          // 1024
    float* esh  = sm + 14336;          // 1536
    float* kvs  = sm + 15872;          // 8192
    float* S2t  = sm + 24064;          // 512
    unsigned char* msh = (unsigned char*)(sm + 24576);  // 2048 B
    // total 25088 floats = 100352 bytes

    const int t = threadIdx.x;
    const int warp = t >> 5, lane = t & 31;
    const int b = blockIdx.y;
    const int i0 = blockIdx.x * ITILE;
    const int ii = warp >> 1;
    const int ch = warp & 1;

    // ---- stage q rows ----
    ((float4*)qs)[t] = ((const float4*)&g_q[(b * NN + i0) * DIN])[t];

    // ---- mask dtype detection (deterministic, same data every block) ----
    {
        unsigned int v0 = mask_raw[t];
        unsigned int v1 = mask_raw[t + 256];
        int weird = (v0 > 1u && v0 != 0x3F800000u) || (v1 > 1u && v1 != 0x3F800000u);
        int flt   = (v0 == 0x3F800000u) || (v1 == 0x3F800000u);
        weird = __syncthreads_or(weird);
        flt   = __syncthreads_or(flt);
        const int mode = weird ? 2 : (flt ? 1 : 0);

        const int base = (b * NN + i0) * NN;
        if (mode == 2) {
            ((unsigned int*)msh)[t]       = mask_raw[(base >> 2) + t];
            ((unsigned int*)msh)[t + 256] = mask_raw[(base >> 2) + t + 256];
        } else if (mode == 1) {
            const float* mf = (const float*)mask_raw + base;
            #pragma unroll
            for (int l = 0; l < 8; l++)
                msh[t + l * 256] = (mf[t + l * 256] != 0.0f);
        } else {
            const unsigned int* mi = mask_raw + base;
            #pragma unroll
            for (int l = 0; l < 8; l++)
                msh[t + l * 256] = (mi[t + l * 256] != 0u);
        }
    }

    // ---- per-lane packed weights (bias MLP) ----
    u64 W1p[EDIM][2], b1p[2], W2p[4][2];
    #pragma unroll
    for (int p = 0; p < 2; p++) {
        int cc0 = ch * 128 + lane + 64 * p;
        int cc1 = cc0 + 32;
        b1p[p] = pack2(beb1[cc0], beb1[cc1]);
        #pragma unroll
        for (int a = 0; a < EDIM; a++)
            W1p[a][p] = pack2(Web1[a * DIN + cc0], Web1[a * DIN + cc1]);
    }
    #pragma unroll
    for (int idx4 = 0; idx4 < 4; idx4++) {
        int p = idx4 >> 1, hi = idx4 & 1;
        int cc = ch * 128 + lane + 64 * p + 32 * hi;
        W2p[idx4][0] = pack2(Web2[cc * NH + 0], Web2[cc * NH + 1]);
        W2p[idx4][1] = pack2(Web2[cc * NH + 2], Web2[cc * NH + 3]);
    }
    const float b20 = beb2[0], b21 = beb2[1], b22 = beb2[2], b23 = beb2[3];
    __syncthreads();

    // hoist this row's q into registers (ch==0 warps compute qk)
    float qreg[NH][2];
    if (ch == 0) {
        #pragma unroll
        for (int h = 0; h < NH; h++) {
            qreg[h][0] = qs[ii * DIN + h * 64 + lane];
            qreg[h][1] = qs[ii * DIN + h * 64 + lane + 32];
        }
    }

    // =================== PASS 1: sim + edge bias ===================
    for (int jt = 0; jt < NN; jt += JTILE) {
        {
            const float4* src = (const float4*)&g_k[(b * NN + jt) * DIN];
            float4* dst = (float4*)kvs;
            #pragma unroll
            for (int l = 0; l < 8; l++) dst[t + l * 256] = src[t + l * 256];
        }
        for (int idx = t; idx < ITILE * JTILE * EDIM; idx += 256) {
            int r = idx / EDIM, a = idx - r * EDIM;
            int e_ii = r >> 5, jj = r & 31;
            esh[r * ESTRIDE + a] =
                edge_attr[((size_t)(b * NN + i0 + e_ii) * NN + jt + jj) * EDIM + a];
        }
        __syncthreads();

        int pj = -1;
        u64 p01 = 0ull, p23 = 0ull;
        const int hsel = lane >> 3;
        const int lead = ((lane & 7) == 0);
        const float b2h = (hsel == 0) ? b20 : (hsel == 1) ? b21 : (hsel == 2) ? b22 : b23;

        for (int jj = 0; jj < JTILE; jj++) {
            const int j = jt + jj;
            if (!msh[ii * NN + j]) {
                if (lead) {
                    if (ch == 0) S[(ii * NH + hsel) * NN + j] = NEGMAX;
                    else         S2t[(ii * NH + hsel) * JTILE + jj] = 0.f;
                }
                continue;
            }
            const float* er = esh + (ii * JTILE + jj) * ESTRIDE;
            float4 ef0 = *(const float4*)er;
            float4 ef1 = *(const float4*)(er + 4);
            float4 ef2 = *(const float4*)(er + 8);
            float e[EDIM] = {ef0.x, ef0.y, ef0.z, ef0.w, ef1.x, ef1.y, ef1.z, ef1.w,
                             ef2.x, ef2.y, ef2.z};

            u64 red01, red23;
            if (ch == 0) {
                const float* kr = kvs + jj * DIN;
                float r0 = SCALE_F * (qreg[0][0] * kr[lane] + qreg[0][1] * kr[lane + 32]);
                float r1 = SCALE_F * (qreg[1][0] * kr[64 + lane] + qreg[1][1] * kr[96 + lane]);
                float r2 = SCALE_F * (qreg[2][0] * kr[128 + lane] + qreg[2][1] * kr[160 + lane]);
                float r3 = SCALE_F * (qreg[3][0] * kr[192 + lane] + qreg[3][1] * kr[224 + lane]);
                red01 = pack2(r0, r1);
                red23 = pack2(r2, r3);
            } else {
                red01 = 0ull;
                red23 = 0ull;
            }

            u64 s2a = b1p[0], s2b = b1p[1];
            #pragma unroll
            for (int a = 0; a < EDIM; a++) {
                u64 ea = pack2(e[a], e[a]);
                s2a = fma2(ea, W1p[a][0], s2a);
                s2b = fma2(ea, W1p[a][1], s2b);
            }
            float sA, sB, sC, sD;
            unpack2(s2a, sA, sB);
            unpack2(s2b, sC, sD);
            u64 gA = pack2(gelu_fast(sA), gelu_fast(sA));
            u64 gB = pack2(gelu_fast(sB), gelu_fast(sB));
            u64 gC = pack2(gelu_fast(sC), gelu_fast(sC));
            u64 gD = pack2(gelu_fast(sD), gelu_fast(sD));
            red01 = fma2(gA, W2p[0][0], red01);  red23 = fma2(gA, W2p[0][1], red23);
            red01 = fma2(gB, W2p[1][0], red01);  red23 = fma2(gB, W2p[1][1], red23);
            red01 = fma2(gC, W2p[2][0], red01);  red23 = fma2(gC, W2p[2][1], red23);
            red01 = fma2(gD, W2p[3][0], red01);  red23 = fma2(gD, W2p[3][1], red23);

            if (pj < 0) { pj = j; p01 = red01; p23 = red23; continue; }

            float a0, a1, a2, a3, c0, c1, c2, c3;
            unpack2(p01, a0, a1); unpack2(p23, a2, a3);
            unpack2(red01, c0, c1); unpack2(red23, c2, c3);
            #pragma unroll
            for (int off = 16; off >= 8; off >>= 1) {
                a0 += __shfl_xor_sync(0xffffffffu, a0, off);
                c0 += __shfl_xor_sync(0xffffffffu, c0, off);
                a1 += __shfl_xor_sync(0xffffffffu, a1, off);
                c1 += __shfl_xor_sync(0xffffffffu, c1, off);
                a2 += __shfl_xor_sync(0xffffffffu, a2, off);
                c2 += __shfl_xor_sync(0xffffffffu, c2, off);
                a3 += __shfl_xor_sync(0xffffffffu, a3, off);
                c3 += __shfl_xor_sync(0xffffffffu, c3, off);
            }
            float wA = (hsel == 0) ? a0 : (hsel == 1) ? a1 : (hsel == 2) ? a2 : a3;
            float wB = (hsel == 0) ? c0 : (hsel == 1) ? c1 : (hsel == 2) ? c2 : c3;
            #pragma unroll
            for (int off = 4; off > 0; off >>= 1) {
                wA += __shfl_xor_sync(0xffffffffu, wA, off);
                wB += __shfl_xor_sync(0xffffffffu, wB, off);
            }
            if (lead) {
                if (ch == 0) {
                    S[(ii * NH + hsel) * NN + pj] = wA + b2h;
                    S[(ii * NH + hsel) * NN + j]  = wB + b2h;
                } else {
                    S2t[(ii * NH + hsel) * JTILE + (pj - jt)] = wA;
                    S2t[(ii * NH + hsel) * JTILE + jj]        = wB;
                }
            }
            pj = -1;
        }
        if (pj >= 0) {
            float a0, a1, a2, a3;
            unpack2(p01, a0, a1); unpack2(p23, a2, a3);
            #pragma unroll
            for (int off = 16; off >= 8; off >>= 1) {
                a0 += __shfl_xor_sync(0xffffffffu, a0, off);
                a1 += __shfl_xor_sync(0xffffffffu, a1, off);
                a2 += __shfl_xor_sync(0xffffffffu, a2, off);
                a3 += __shfl_xor_sync(0xffffffffu, a3, off);
            }
            float wA = (hsel == 0) ? a0 : (hsel == 1) ? a1 : (hsel == 2) ? a2 : a3;
            #pragma unroll
            for (int off = 4; off > 0; off >>= 1)
                wA += __shfl_xor_sync(0xffffffffu, wA, off);
            if (lead) {
                if (ch == 0) S[(ii * NH + hsel) * NN + pj] = wA + b2h;
                else         S2t[(ii * NH + hsel) * JTILE + (pj - jt)] = wA;
            }
        }
        __syncthreads();
        #pragma unroll
        for (int l = 0; l < 2; l++) {
            int idx = t + l * 256;
            int r = idx >> 5, jj = idx & 31;
            S[r * NN + jt + jj] += S2t[idx];
        }
        __syncthreads();
    }

    // =================== PASS 2: softmax (8 warps x 2 rows) ===================
    #pragma unroll
    for (int rr = 0; rr < 2; rr++) {
        const int row = warp * 2 + rr;
        float vals[16];
        float m = NEGMAX;
        #pragma unroll
        for (int kk = 0; kk < 16; kk++) {
            vals[kk] = S[row * NN + lane + kk * 32];
            m = fmaxf(m, vals[kk]);
        }
        #pragma unroll
        for (int off = 16; off > 0; off >>= 1)
            m = fmaxf(m, __shfl_xor_sync(0xffffffffu, m, off));
        float sum = 0.f;
        #pragma unroll
        for (int kk = 0; kk < 16; kk++) {
            float p = __expf(vals[kk] - m);
            vals[kk] = p;
            sum += p;
        }
        #pragma unroll
        for (int off = 16; off > 0; off >>= 1)
            sum += __shfl_xor_sync(0xffffffffu, sum, off);
        const float inv = 1.0f / sum;
        #pragma unroll
        for (int kk = 0; kk < 16; kk++)
            S[row * NN + lane + kk * 32] = vals[kk] * inv;
    }
    __syncthreads();

    // ---- vectorized attn store (only when the harness checks it) ----
    if (store_attn) {
        #pragma unroll
        for (int l = 0; l < 8; l++) {
            int idx = t + l * 256;
            int row = idx >> 7;
            int col4 = idx & 127;
            int rii = row >> 2, h = row & 3;
            float4 v = ((const float4*)S)[idx];
            ((float4*)(attn_out + (((size_t)b * NH + h) * NN + (i0 + rii)) * NN))[col4] = v;
        }
    }
    __syncthreads();

    // =================== PASS 3: t and attn@v accumulation ===================
    u64 W1p3[EDIM][2], b1p3[2];
    #pragma unroll
    for (int p = 0; p < 2; p++) {
        int cc0 = ch * 128 + lane + 64 * p;
        int cc1 = cc0 + 32;
        b1p3[p] = pack2(bev1[cc0], bev1[cc1]);
        #pragma unroll
        for (int a = 0; a < EDIM; a++)
            W1p3[a][p] = pack2(Wev1[a * DIN + cc0], Wev1[a * DIN + cc1]);
    }
    u64 tr2[NH][2];
    #pragma unroll
    for (int h = 0; h < NH; h++) { tr2[h][0] = 0ull; tr2[h][1] = 0ull; }
    float va[2][2] = {};

    for (int jt = 0; jt < NN; jt += JTILE) {
        {
            const float4* src = (const float4*)&g_v[(b * NN + jt) * DIN];
            float4* dst = (float4*)kvs;
            #pragma unroll
            for (int l = 0; l < 8; l++) dst[t + l * 256] = src[t + l * 256];
        }
        for (int idx = t; idx < ITILE * JTILE * EDIM; idx += 256) {
            int r = idx / EDIM, a = idx - r * EDIM;
            int e_ii = r >> 5, jj = r & 31;
            esh[r * ESTRIDE + a] =
                edge_attr[((size_t)(b * NN + i0 + e_ii) * NN + jt + jj) * EDIM + a];
        }
        __syncthreads();

        int pj = -1;
        u64 ps2a = 0ull, ps2b = 0ull;

        for (int jj = 0; jj < JTILE; jj++) {
            const int j = jt + jj;
            if (!msh[ii * NN + j]) continue;

            const float* er = esh + (ii * JTILE + jj) * ESTRIDE;
            float4 ef0 = *(const float4*)er;
            float4 ef1 = *(const float4*)(er + 4);
            float4 ef2 = *(const float4*)(er + 8);
            float e[EDIM] = {ef0.x, ef0.y, ef0.z, ef0.w, ef1.x, ef1.y, ef1.z, ef1.w,
                             ef2.x, ef2.y, ef2.z};

            u64 s2a = b1p3[0], s2b = b1p3[1];
            #pragma unroll
            for (int a = 0; a < EDIM; a++) {
                u64 ea = pack2(e[a], e[a]);
                s2a = fma2(ea, W1p3[a][0], s2a);
                s2b = fma2(ea, W1p3[a][1], s2b);
            }

            if (pj < 0) { pj = j; ps2a = s2a; ps2b = s2b; continue; }

            float xA, xB, xC, xD, yA, yB, yC, yD;
            unpack2(ps2a, xA, xB); unpack2(ps2b, xC, xD);
            unpack2(s2a, yA, yB);  unpack2(s2b, yC, yD);
            u64 gA2a = pack2(gelu_fast(xA), gelu_fast(xB));
            u64 gA2b = pack2(gelu_fast(xC), gelu_fast(xD));
            u64 gB2a = pack2(gelu_fast(yA), gelu_fast(yB));
            u64 gB2b = pack2(gelu_fast(yC), gelu_fast(yD));

            #pragma unroll
            for (int h = 0; h < NH; h++) {
                float aAh = S[(ii * NH + h) * NN + pj];
                float aBh = S[(ii * NH + h) * NN + j];
                u64 pA = pack2(aAh, aAh);
                u64 pB = pack2(aBh, aBh);
                tr2[h][0] = fma2(pA, gA2a, tr2[h][0]);
                tr2[h][1] = fma2(pA, gA2b, tr2[h][1]);
                tr2[h][0] = fma2(pB, gB2a, tr2[h][0]);
                tr2[h][1] = fma2(pB, gB2b, tr2[h][1]);
            }
            {
                const float* vrA = kvs + (pj - jt) * DIN;
                const float* vrB = kvs + jj * DIN;
                #pragma unroll
                for (int hh = 0; hh < 2; hh++) {
                    const int h = ch * 2 + hh;
                    float aAh = S[(ii * NH + h) * NN + pj];
                    float aBh = S[(ii * NH + h) * NN + j];
                    va[hh][0] += aAh * vrA[h * 64 + lane] + aBh * vrB[h * 64 + lane];
                    va[hh][1] += aAh * vrA[h * 64 + lane + 32] + aBh * vrB[h * 64 + lane + 32];
                }
            }
            pj = -1;
        }
        if (pj >= 0) {
            float xA, xB, xC, xD;
            unpack2(ps2a, xA, xB); unpack2(ps2b, xC, xD);
            u64 gA2a = pack2(gelu_fast(xA), gelu_fast(xB));
            u64 gA2b = pack2(gelu_fast(xC), gelu_fast(xD));
            #pragma unroll
            for (int h = 0; h < NH; h++) {
                float aAh = S[(ii * NH + h) * NN + pj];
                u64 pA = pack2(aAh, aAh);
                tr2[h][0] = fma2(pA, gA2a, tr2[h][0]);
                tr2[h][1] = fma2(pA, gA2b, tr2[h][1]);
            }
            const float* vrA = kvs + (pj - jt) * DIN;
            #pragma unroll
            for (int hh = 0; hh < 2; hh++) {
                const int h = ch * 2 + hh;
                float aAh = S[(ii * NH + h) * NN + pj];
                va[hh][0] += aAh * vrA[h * 64 + lane];
                va[hh][1] += aAh * vrA[h * 64 + lane + 32];
            }
        }
        __syncthreads();
    }

    // dump accumulators (chain order: p0_lo, p0_hi, p1_lo, p1_hi)
    #pragma unroll
    for (int h = 0; h < NH; h++) {
        float tA, tB, tC, tD;
        unpack2(tr2[h][0], tA, tB);
        unpack2(tr2[h][1], tC, tD);
        float* trow = &tsh[(ii * NH + h) * DIN + ch * 128 + lane];
        trow[0]  = tA;
        trow[32] = tB;
        trow[64] = tC;
        trow[96] = tD;
    }
    #pragma unroll
    for (int hh = 0; hh < 2; hh++) {
        const int h = ch * 2 + hh;
        vacc[ii * DIN + h * 64 + lane]      = va[hh][0];
        vacc[ii * DIN + h * 64 + lane + 32] = va[hh][1];
    }
    __syncthreads();

    // =================== FINAL: o_inner = vacc + t@Wev2 + bev2 ===================
    {
        const int col = t;
        const int h = col >> 6;
        const float bcol = bev2[col];
        #pragma unroll
        for (int i2 = 0; i2 < ITILE; i2++) {
            const float* trow = &tsh[(i2 * NH + h) * DIN];
            float acc0 = 0.f, acc1 = 0.f, acc2 = 0.f, acc3 = 0.f;
            #pragma unroll 4
            for (int cc = 0; cc < DIN; cc += 4) {
                acc0 += trow[cc]     * Wev2[(cc)     * DIN + col];
                acc1 += trow[cc + 1] * Wev2[(cc + 1) * DIN + col];
                acc2 += trow[cc + 2] * Wev2[(cc + 2) * DIN + col];
                acc3 += trow[cc + 3] * Wev2[(cc + 3) * DIN + col];
            }
            g_oi[(b * NN + i0 + i2) * DIN + col] =
                ((acc0 + acc1) + (acc2 + acc3)) + vacc[i2 * DIN + col] + bcol;
        }
    }
}

// ============================================================
extern "C" void kernel_launch(void* const* d_in, const int* in_sizes, int n_in,
                              void* d_out, int out_size)
{
    const float* x           = (const float*)d_in[0];
    const void*  mask_raw    = d_in[1];
    const float* ea          = (const float*)d_in[2];
    const float* Wq          = (const float*)d_in[3];
    const float* Wk          = (const float*)d_in[4];
    const float* Wv          = (const float*)d_in[5];
    const float* Web1        = (const float*)d_in[6];
    const float* beb1        = (const float*)d_in[7];
    const float* Web2        = (const float*)d_in[8];
    const float* beb2        = (const float*)d_in[9];
    const float* Wev1        = (const float*)d_in[10];
    const float* bev1        = (const float*)d_in[11];
    const float* Wev2        = (const float*)d_in[12];
    const float* bev2        = (const float*)d_in[13];
    const float* Wo          = (const float*)d_in[14];
    const float* bo          = (const float*)d_in[15];

    float* out = (float*)d_out;
    const int out_elems  = BB * NN * QDIM;              // 524288
    const int attn_elems = BB * NH * NN * NN;           // 2097152

    float *oip, *attn_fb;
    cudaGetSymbolAddress((void**)&oip, g_oi);
    cudaGetSymbolAddress((void**)&attn_fb, g_attn_scratch);

    const int store_attn = (out_size >= out_elems + attn_elems) ? 1 : 0;
    float* attn = store_attn ? (out + out_elems) : attn_fb;

    const int smem_bytes = 25088 * 4;   // 100352
    cudaFuncSetAttribute(attn_fused, cudaFuncAttributeMaxDynamicSharedMemorySize, smem_bytes);

    // fused q/k/v projections: 3 sel x 4 n-tiles x 16 m-tiles = 192 blocks
    qkv_gemm<<<dim3(12, (BB * NN) / 64), 256>>>(x, Wq, Wk, Wv);

    // fused attention + edge MLPs (mask handling inlined; 256 thr, 2 blocks/SM)
    attn_fused<<<dim3(NN / ITILE, BB), 256, smem_bytes>>>(
        ea, (const unsigned int*)mask_raw, Web1, beb1, Web2, beb2,
        Wev1, bev1, Wev2, bev2, attn, store_attn);

    // final projection: out = o_inner @ Wo + bo  (8 x 16 = 128 blocks, 64x64)
    gemm_tiled<<<dim3(QDIM / 64, (BB * NN) / 64), 256>>>(oip, Wo, bo, out, BB * NN, DIN, QDIM);
}

// round 15
// speedup vs baseline: 1.4134x; 1.0202x over previous
#include <cuda_runtime.h>
#include <math.h>

#define BB 2
#define NN 512
#define QDIM 512
#define EDIM 11
#define NH 4
#define DHEAD 64
#define DIN 256          // INNER = NH*DHEAD
#define SCALE_F 0.125f   // 64^-0.5
#define NEGMAX -3.402823466e38f

#define ITILE 4
#define JTILE 32
#define ESTRIDE 12       // padded edge-feature row stride

// -------- device scratch (no allocations allowed) --------
__device__ float g_q[BB * NN * DIN];
__device__ float g_k[BB * NN * DIN];
__device__ float g_v[BB * NN * DIN];
__device__ float g_oi[BB * NN * DIN];
__device__ float g_attn_scratch[BB * NH * NN * NN];

typedef unsigned long long u64;

// ---- packed fp32x2 helpers ----
__device__ __forceinline__ u64 pack2(float lo, float hi) {
    u64 r; asm("mov.b64 %0, {%1, %2};" : "=l"(r) : "f"(lo), "f"(hi)); return r;
}
__device__ __forceinline__ void unpack2(u64 v, float& lo, float& hi) {
    asm("mov.b64 {%0, %1}, %2;" : "=f"(lo), "=f"(hi) : "l"(v));
}
__device__ __forceinline__ u64 fma2(u64 a, u64 b, u64 c) {
    u64 d; asm("fma.rn.f32x2 %0, %1, %2, %3;" : "=l"(d) : "l"(a), "l"(b), "l"(c)); return d;
}

// lean fast GELU (validated: total rel_err ~5e-7)
__device__ __forceinline__ float gelu_fast(float x) {
    float x2 = x * x;
    float u = x * fmaf(0.0356774081f, x2, 0.7978845608f);
    float th;
    asm("tanh.approx.f32 %0, %1;" : "=f"(th) : "f"(u));
    float hx = 0.5f * x;
    return fmaf(hx, th, hx);
}

// ============================================================
// GEMM 64x64 tile, 256 threads, 4x4/thread, K-tile 16,
// double-buffered smem pipeline (1 barrier per k-tile).
// ============================================================
__device__ __forceinline__ void gemm_body(
    const float* __restrict__ A, const float* __restrict__ W,
    const float* __restrict__ bias, float* __restrict__ C,
    int M, int K, int Nc, int m0, int n0)
{
    __shared__ float As[2][16][68];
    __shared__ float Bs[2][16][68];
    const int t = threadIdx.x;
    const int r = t >> 4, c = t & 15;
    const int amm = t >> 2, akk4 = (t & 3) * 4;   // A-load coords
    const int bkk = t >> 4, bnn4 = (t & 15) * 4;  // B-load coords
    float acc[4][4] = {};

    const int ntiles = K >> 4;

    // prologue: load tile 0 into buffer 0
    float4 a_next = *(const float4*)&A[(m0 + amm) * K + akk4];
    float4 b_next = *(const float4*)&W[bkk * Nc + n0 + bnn4];
    As[0][akk4 + 0][amm] = a_next.x;
    As[0][akk4 + 1][amm] = a_next.y;
    As[0][akk4 + 2][amm] = a_next.z;
    As[0][akk4 + 3][amm] = a_next.w;
    *(float4*)&Bs[0][bkk][bnn4] = b_next;
    __syncthreads();

    for (int i = 0; i < ntiles; i++) {
        const int buf = i & 1;
        // issue loads for tile i+1 early (latency overlapped with compute)
        if (i + 1 < ntiles) {
            const int k0 = (i + 1) << 4;
            a_next = *(const float4*)&A[(m0 + amm) * K + k0 + akk4];
            b_next = *(const float4*)&W[(k0 + bkk) * Nc + n0 + bnn4];
        }
        #pragma unroll
        for (int kk = 0; kk < 16; kk++) {
            float4 av = *(const float4*)&As[buf][kk][r * 4];
            float4 bv = *(const float4*)&Bs[buf][kk][c * 4];
            acc[0][0] = fmaf(av.x, bv.x, acc[0][0]);
            acc[0][1] = fmaf(av.x, bv.y, acc[0][1]);
            acc[0][2] = fmaf(av.x, bv.z, acc[0][2]);
            acc[0][3] = fmaf(av.x, bv.w, acc[0][3]);
            acc[1][0] = fmaf(av.y, bv.x, acc[1][0]);
            acc[1][1] = fmaf(av.y, bv.y, acc[1][1]);
            acc[1][2] = fmaf(av.y, bv.z, acc[1][2]);
            acc[1][3] = fmaf(av.y, bv.w, acc[1][3]);
            acc[2][0] = fmaf(av.z, bv.x, acc[2][0]);
            acc[2][1] = fmaf(av.z, bv.y, acc[2][1]);
            acc[2][2] = fmaf(av.z, bv.z, acc[2][2]);
            acc[2][3] = fmaf(av.z, bv.w, acc[2][3]);
            acc[3][0] = fmaf(av.w, bv.x, acc[3][0]);
            acc[3][1] = fmaf(av.w, bv.y, acc[3][1]);
            acc[3][2] = fmaf(av.w, bv.z, acc[3][2]);
            acc[3][3] = fmaf(av.w, bv.w, acc[3][3]);
        }
        if (i + 1 < ntiles) {
            const int nbuf = buf ^ 1;
            As[nbuf][akk4 + 0][amm] = a_next.x;
            As[nbuf][akk4 + 1][amm] = a_next.y;
            As[nbuf][akk4 + 2][amm] = a_next.z;
            As[nbuf][akk4 + 3][amm] = a_next.w;
            *(float4*)&Bs[nbuf][bkk][bnn4] = b_next;
            __syncthreads();
        }
    }

    #pragma unroll
    for (int i = 0; i < 4; i++) {
        int m = m0 + r * 4 + i, n = n0 + c * 4;
        float4 v = make_float4(acc[i][0], acc[i][1], acc[i][2], acc[i][3]);
        if (bias) {
            v.x += bias[n];
            v.y += bias[n + 1];
            v.z += bias[n + 2];
            v.w += bias[n + 3];
        }
        *(float4*)&C[m * Nc + n] = v;
    }
}

// fused q/k/v projection: blockIdx.x = sel*4 + ntile (DIN/64 = 4 n-tiles)
__global__ __launch_bounds__(256) void qkv_gemm(
    const float* __restrict__ x,
    const float* __restrict__ Wq, const float* __restrict__ Wk, const float* __restrict__ Wv)
{
    const int sel = blockIdx.x >> 2;
    const int n0 = (blockIdx.x & 3) * 64;
    const int m0 = blockIdx.y * 64;
    const float* W = (sel == 0) ? Wq : (sel == 1) ? Wk : Wv;
    float* C = (sel == 0) ? g_q : (sel == 1) ? g_k : g_v;
    gemm_body(x, W, nullptr, C, BB * NN, QDIM, DIN, m0, n0);
}

__global__ __launch_bounds__(256) void gemm_tiled(
    const float* __restrict__ A, const float* __restrict__ W,
    const float* __restrict__ bias, float* __restrict__ C,
    int M, int K, int Nc)
{
    gemm_body(A, W, bias, C, M, K, Nc, blockIdx.y * 64, blockIdx.x * 64);
}

// ============================================================
// Fused attention (R13/R14, byte-identical hot loops).
// block = (b, 4 query rows), 256 threads, 2 blocks/SM.
// ============================================================
__global__ __launch_bounds__(256, 2) void attn_fused(
    const float* __restrict__ edge_attr,
    const unsigned int* __restrict__ mask_raw,
    const float* __restrict__ Web1, const float* __restrict__ beb1,
    const float* __restrict__ Web2, const float* __restrict__ beb2,
    const float* __restrict__ Wev1, const float* __restrict__ bev1,
    const float* __restrict__ Wev2, const float* __restrict__ bev2,
    float* __restrict__ attn_out, int store_attn)
{
    extern __shared__ float sm[];
    float* qs   = sm;                  // 1024
    float* S    = sm + 1024;           // 8192
    float* tsh  = sm + 9216;           // 4096
    float* vacc = sm + 13312;          // 1024
    float* esh  = sm + 14336;          // 1536
    float* kvs  = sm + 15872;          // 8192
    float* S2t  = sm + 24064;          // 512
    unsigned char* msh = (unsigned char*)(sm + 24576);  // 2048 B
    // total 25088 floats = 100352 bytes

    const int t = threadIdx.x;
    const int warp = t >> 5, lane = t & 31;
    const int b = blockIdx.y;
    const int i0 = blockIdx.x * ITILE;
    const int ii = warp >> 1;
    const int ch = warp & 1;

    // ---- stage q rows ----
    ((float4*)qs)[t] = ((const float4*)&g_q[(b * NN + i0) * DIN])[t];

    // ---- mask dtype detection (deterministic, same data every block) ----
    {
        unsigned int v0 = mask_raw[t];
        unsigned int v1 = mask_raw[t + 256];
        int weird = (v0 > 1u && v0 != 0x3F800000u) || (v1 > 1u && v1 != 0x3F800000u);
        int flt   = (v0 == 0x3F800000u) || (v1 == 0x3F800000u);
        weird = __syncthreads_or(weird);
        flt   = __syncthreads_or(flt);
        const int mode = weird ? 2 : (flt ? 1 : 0);

        const int base = (b * NN + i0) * NN;
        if (mode == 2) {
            ((unsigned int*)msh)[t]       = mask_raw[(base >> 2) + t];
            ((unsigned int*)msh)[t + 256] = mask_raw[(base >> 2) + t + 256];
        } else if (mode == 1) {
            const float* mf = (const float*)mask_raw + base;
            #pragma unroll
            for (int l = 0; l < 8; l++)
                msh[t + l * 256] = (mf[t + l * 256] != 0.0f);
        } else {
            const unsigned int* mi = mask_raw + base;
            #pragma unroll
            for (int l = 0; l < 8; l++)
                msh[t + l * 256] = (mi[t + l * 256] != 0u);
        }
    }

    // ---- per-lane packed weights (bias MLP) ----
    u64 W1p[EDIM][2], b1p[2], W2p[4][2];
    #pragma unroll
    for (int p = 0; p < 2; p++) {
        int cc0 = ch * 128 + lane + 64 * p;
        int cc1 = cc0 + 32;
        b1p[p] = pack2(beb1[cc0], beb1[cc1]);
        #pragma unroll
        for (int a = 0; a < EDIM; a++)
            W1p[a][p] = pack2(Web1[a * DIN + cc0], Web1[a * DIN + cc1]);
    }
    #pragma unroll
    for (int idx4 = 0; idx4 < 4; idx4++) {
        int p = idx4 >> 1, hi = idx4 & 1;
        int cc = ch * 128 + lane + 64 * p + 32 * hi;
        W2p[idx4][0] = pack2(Web2[cc * NH + 0], Web2[cc * NH + 1]);
        W2p[idx4][1] = pack2(Web2[cc * NH + 2], Web2[cc * NH + 3]);
    }
    const float b20 = beb2[0], b21 = beb2[1], b22 = beb2[2], b23 = beb2[3];
    __syncthreads();

    // hoist this row's q into registers (ch==0 warps compute qk)
    float qreg[NH][2];
    if (ch == 0) {
        #pragma unroll
        for (int h = 0; h < NH; h++) {
            qreg[h][0] = qs[ii * DIN + h * 64 + lane];
            qreg[h][1] = qs[ii * DIN + h * 64 + lane + 32];
        }
    }

    // =================== PASS 1: sim + edge bias ===================
    for (int jt = 0; jt < NN; jt += JTILE) {
        {
            const float4* src = (const float4*)&g_k[(b * NN + jt) * DIN];
            float4* dst = (float4*)kvs;
            #pragma unroll
            for (int l = 0; l < 8; l++) dst[t + l * 256] = src[t + l * 256];
        }
        for (int idx = t; idx < ITILE * JTILE * EDIM; idx += 256) {
            int r = idx / EDIM, a = idx - r * EDIM;
            int e_ii = r >> 5, jj = r & 31;
            esh[r * ESTRIDE + a] =
                edge_attr[((size_t)(b * NN + i0 + e_ii) * NN + jt + jj) * EDIM + a];
        }
        __syncthreads();

        int pj = -1;
        u64 p01 = 0ull, p23 = 0ull;
        const int hsel = lane >> 3;
        const int lead = ((lane & 7) == 0);
        const float b2h = (hsel == 0) ? b20 : (hsel == 1) ? b21 : (hsel == 2) ? b22 : b23;

        for (int jj = 0; jj < JTILE; jj++) {
            const int j = jt + jj;
            if (!msh[ii * NN + j]) {
                if (lead) {
                    if (ch == 0) S[(ii * NH + hsel) * NN + j] = NEGMAX;
                    else         S2t[(ii * NH + hsel) * JTILE + jj] = 0.f;
                }
                continue;
            }
            const float* er = esh + (ii * JTILE + jj) * ESTRIDE;
            float4 ef0 = *(const float4*)er;
            float4 ef1 = *(const float4*)(er + 4);
            float4 ef2 = *(const float4*)(er + 8);
            float e[EDIM] = {ef0.x, ef0.y, ef0.z, ef0.w, ef1.x, ef1.y, ef1.z, ef1.w,
                             ef2.x, ef2.y, ef2.z};

            u64 red01, red23;
            if (ch == 0) {
                const float* kr = kvs + jj * DIN;
                float r0 = SCALE_F * (qreg[0][0] * kr[lane] + qreg[0][1] * kr[lane + 32]);
                float r1 = SCALE_F * (qreg[1][0] * kr[64 + lane] + qreg[1][1] * kr[96 + lane]);
                float r2 = SCALE_F * (qreg[2][0] * kr[128 + lane] + qreg[2][1] * kr[160 + lane]);
                float r3 = SCALE_F * (qreg[3][0] * kr[192 + lane] + qreg[3][1] * kr[224 + lane]);
                red01 = pack2(r0, r1);
                red23 = pack2(r2, r3);
            } else {
                red01 = 0ull;
                red23 = 0ull;
            }

            u64 s2a = b1p[0], s2b = b1p[1];
            #pragma unroll
            for (int a = 0; a < EDIM; a++) {
                u64 ea = pack2(e[a], e[a]);
                s2a = fma2(ea, W1p[a][0], s2a);
                s2b = fma2(ea, W1p[a][1], s2b);
            }
            float sA, sB, sC, sD;
            unpack2(s2a, sA, sB);
            unpack2(s2b, sC, sD);
            u64 gA = pack2(gelu_fast(sA), gelu_fast(sA));
            u64 gB = pack2(gelu_fast(sB), gelu_fast(sB));
            u64 gC = pack2(gelu_fast(sC), gelu_fast(sC));
            u64 gD = pack2(gelu_fast(sD), gelu_fast(sD));
            red01 = fma2(gA, W2p[0][0], red01);  red23 = fma2(gA, W2p[0][1], red23);
            red01 = fma2(gB, W2p[1][0], red01);  red23 = fma2(gB, W2p[1][1], red23);
            red01 = fma2(gC, W2p[2][0], red01);  red23 = fma2(gC, W2p[2][1], red23);
            red01 = fma2(gD, W2p[3][0], red01);  red23 = fma2(gD, W2p[3][1], red23);

            if (pj < 0) { pj = j; p01 = red01; p23 = red23; continue; }

            float a0, a1, a2, a3, c0, c1, c2, c3;
            unpack2(p01, a0, a1); unpack2(p23, a2, a3);
            unpack2(red01, c0, c1); unpack2(red23, c2, c3);
            #pragma unroll
            for (int off = 16; off >= 8; off >>= 1) {
                a0 += __shfl_xor_sync(0xffffffffu, a0, off);
                c0 += __shfl_xor_sync(0xffffffffu, c0, off);
                a1 += __shfl_xor_sync(0xffffffffu, a1, off);
                c1 += __shfl_xor_sync(0xffffffffu, c1, off);
                a2 += __shfl_xor_sync(0xffffffffu, a2, off);
                c2 += __shfl_xor_sync(0xffffffffu, c2, off);
                a3 += __shfl_xor_sync(0xffffffffu, a3, off);
                c3 += __shfl_xor_sync(0xffffffffu, c3, off);
            }
            float wA = (hsel == 0) ? a0 : (hsel == 1) ? a1 : (hsel == 2) ? a2 : a3;
            float wB = (hsel == 0) ? c0 : (hsel == 1) ? c1 : (hsel == 2) ? c2 : c3;
            #pragma unroll
            for (int off = 4; off > 0; off >>= 1) {
                wA += __shfl_xor_sync(0xffffffffu, wA, off);
                wB += __shfl_xor_sync(0xffffffffu, wB, off);
            }
            if (lead) {
                if (ch == 0) {
                    S[(ii * NH + hsel) * NN + pj] = wA + b2h;
                    S[(ii * NH + hsel) * NN + j]  = wB + b2h;
                } else {
                    S2t[(ii * NH + hsel) * JTILE + (pj - jt)] = wA;
                    S2t[(ii * NH + hsel) * JTILE + jj]        = wB;
                }
            }
            pj = -1;
        }
        if (pj >= 0) {
            float a0, a1, a2, a3;
            unpack2(p01, a0, a1); unpack2(p23, a2, a3);
            #pragma unroll
            for (int off = 16; off >= 8; off >>= 1) {
                a0 += __shfl_xor_sync(0xffffffffu, a0, off);
                a1 += __shfl_xor_sync(0xffffffffu, a1, off);
                a2 += __shfl_xor_sync(0xffffffffu, a2, off);
                a3 += __shfl_xor_sync(0xffffffffu, a3, off);
            }
            float wA = (hsel == 0) ? a0 : (hsel == 1) ? a1 : (hsel == 2) ? a2 : a3;
            #pragma unroll
            for (int off = 4; off > 0; off >>= 1)
                wA += __shfl_xor_sync(0xffffffffu, wA, off);
            if (lead) {
                if (ch == 0) S[(ii * NH + hsel) * NN + pj] = wA + b2h;
                else         S2t[(ii * NH + hsel) * JTILE + (pj - jt)] = wA;
            }
        }
        __syncthreads();
        #pragma unroll
        for (int l = 0; l < 2; l++) {
            int idx = t + l * 256;
            int r = idx >> 5, jj = idx & 31;
            S[r * NN + jt + jj] += S2t[idx];
        }
        __syncthreads();
    }

    // =================== PASS 2: softmax (8 warps x 2 rows) ===================
    #pragma unroll
    for (int rr = 0; rr < 2; rr++) {
        const int row = warp * 2 + rr;
        float vals[16];
        float m = NEGMAX;
        #pragma unroll
        for (int kk = 0; kk < 16; kk++) {
            vals[kk] = S[row * NN + lane + kk * 32];
            m = fmaxf(m, vals[kk]);
        }
        #pragma unroll
        for (int off = 16; off > 0; off >>= 1)
            m = fmaxf(m, __shfl_xor_sync(0xffffffffu, m, off));
        float sum = 0.f;
        #pragma unroll
        for (int kk = 0; kk < 16; kk++) {
            float p = __expf(vals[kk] - m);
            vals[kk] = p;
            sum += p;
        }
        #pragma unroll
        for (int off = 16; off > 0; off >>= 1)
            sum += __shfl_xor_sync(0xffffffffu, sum, off);
        const float inv = 1.0f / sum;
        #pragma unroll
        for (int kk = 0; kk < 16; kk++)
            S[row * NN + lane + kk * 32] = vals[kk] * inv;
    }
    __syncthreads();

    // ---- vectorized attn store (only when the harness checks it) ----
    if (store_attn) {
        #pragma unroll
        for (int l = 0; l < 8; l++) {
            int idx = t + l * 256;
            int row = idx >> 7;
            int col4 = idx & 127;
            int rii = row >> 2, h = row & 3;
            float4 v = ((const float4*)S)[idx];
            ((float4*)(attn_out + (((size_t)b * NH + h) * NN + (i0 + rii)) * NN))[col4] = v;
        }
    }
    __syncthreads();

    // =================== PASS 3: t and attn@v accumulation ===================
    u64 W1p3[EDIM][2], b1p3[2];
    #pragma unroll
    for (int p = 0; p < 2; p++) {
        int cc0 = ch * 128 + lane + 64 * p;
        int cc1 = cc0 + 32;
        b1p3[p] = pack2(bev1[cc0], bev1[cc1]);
        #pragma unroll
        for (int a = 0; a < EDIM; a++)
            W1p3[a][p] = pack2(Wev1[a * DIN + cc0], Wev1[a * DIN + cc1]);
    }
    u64 tr2[NH][2];
    #pragma unroll
    for (int h = 0; h < NH; h++) { tr2[h][0] = 0ull; tr2[h][1] = 0ull; }
    float va[2][2] = {};

    for (int jt = 0; jt < NN; jt += JTILE) {
        {
            const float4* src = (const float4*)&g_v[(b * NN + jt) * DIN];
            float4* dst = (float4*)kvs;
            #pragma unroll
            for (int l = 0; l < 8; l++) dst[t + l * 256] = src[t + l * 256];
        }
        for (int idx = t; idx < ITILE * JTILE * EDIM; idx += 256) {
            int r = idx / EDIM, a = idx - r * EDIM;
            int e_ii = r >> 5, jj = r & 31;
            esh[r * ESTRIDE + a] =
                edge_attr[((size_t)(b * NN + i0 + e_ii) * NN + jt + jj) * EDIM + a];
        }
        __syncthreads();

        int pj = -1;
        u64 ps2a = 0ull, ps2b = 0ull;

        for (int jj = 0; jj < JTILE; jj++) {
            const int j = jt + jj;
            if (!msh[ii * NN + j]) continue;

            const float* er = esh + (ii * JTILE + jj) * ESTRIDE;
            float4 ef0 = *(const float4*)er;
            float4 ef1 = *(const float4*)(er + 4);
            float4 ef2 = *(const float4*)(er + 8);
            float e[EDIM] = {ef0.x, ef0.y, ef0.z, ef0.w, ef1.x, ef1.y, ef1.z, ef1.w,
                             ef2.x, ef2.y, ef2.z};

            u64 s2a = b1p3[0], s2b = b1p3[1];
            #pragma unroll
            for (int a = 0; a < EDIM; a++) {
                u64 ea = pack2(e[a], e[a]);
                s2a = fma2(ea, W1p3[a][0], s2a);
                s2b = fma2(ea, W1p3[a][1], s2b);
            }

            if (pj < 0) { pj = j; ps2a = s2a; ps2b = s2b; continue; }

            float xA, xB, xC, xD, yA, yB, yC, yD;
            unpack2(ps2a, xA, xB); unpack2(ps2b, xC, xD);
            unpack2(s2a, yA, yB);  unpack2(s2b, yC, yD);
            u64 gA2a = pack2(gelu_fast(xA), gelu_fast(xB));
            u64 gA2b = pack2(gelu_fast(xC), gelu_fast(xD));
            u64 gB2a = pack2(gelu_fast(yA), gelu_fast(yB));
            u64 gB2b = pack2(gelu_fast(yC), gelu_fast(yD));

            #pragma unroll
            for (int h = 0; h < NH; h++) {
                float aAh = S[(ii * NH + h) * NN + pj];
                float aBh = S[(ii * NH + h) * NN + j];
                u64 pA = pack2(aAh, aAh);
                u64 pB = pack2(aBh, aBh);
                tr2[h][0] = fma2(pA, gA2a, tr2[h][0]);
                tr2[h][1] = fma2(pA, gA2b, tr2[h][1]);
                tr2[h][0] = fma2(pB, gB2a, tr2[h][0]);
                tr2[h][1] = fma2(pB, gB2b, tr2[h][1]);
            }
            {
                const float* vrA = kvs + (pj - jt) * DIN;
                const float* vrB = kvs + jj * DIN;
                #pragma unroll
                for (int hh = 0; hh < 2; hh++) {
                    const int h = ch * 2 + hh;
                    float aAh = S[(ii * NH + h) * NN + pj];
                    float aBh = S[(ii * NH + h) * NN + j];
                    va[hh][0] += aAh * vrA[h * 64 + lane] + aBh * vrB[h * 64 + lane];
                    va[hh][1] += aAh * vrA[h * 64 + lane + 32] + aBh * vrB[h * 64 + lane + 32];
                }
            }
            pj = -1;
        }
        if (pj >= 0) {
            float xA, xB, xC, xD;
            unpack2(ps2a, xA, xB); unpack2(ps2b, xC, xD);
            u64 gA2a = pack2(gelu_fast(xA), gelu_fast(xB));
            u64 gA2b = pack2(gelu_fast(xC), gelu_fast(xD));
            #pragma unroll
            for (int h = 0; h < NH; h++) {
                float aAh = S[(ii * NH + h) * NN + pj];
                u64 pA = pack2(aAh, aAh);
                tr2[h][0] = fma2(pA, gA2a, tr2[h][0]);
                tr2[h][1] = fma2(pA, gA2b, tr2[h][1]);
            }
            const float* vrA = kvs + (pj - jt) * DIN;
            #pragma unroll
            for (int hh = 0; hh < 2; hh++) {
                const int h = ch * 2 + hh;
                float aAh = S[(ii * NH + h) * NN + pj];
                va[hh][0] += aAh * vrA[h * 64 + lane];
                va[hh][1] += aAh * vrA[h * 64 + lane + 32];
            }
        }
        __syncthreads();
    }

    // dump accumulators (chain order: p0_lo, p0_hi, p1_lo, p1_hi)
    #pragma unroll
    for (int h = 0; h < NH; h++) {
        float tA, tB, tC, tD;
        unpack2(tr2[h][0], tA, tB);
        unpack2(tr2[h][1], tC, tD);
        float* trow = &tsh[(ii * NH + h) * DIN + ch * 128 + lane];
        trow[0]  = tA;
        trow[32] = tB;
        trow[64] = tC;
        trow[96] = tD;
    }
    #pragma unroll
    for (int hh = 0; hh < 2; hh++) {
        const int h = ch * 2 + hh;
        vacc[ii * DIN + h * 64 + lane]      = va[hh][0];
        vacc[ii * DIN + h * 64 + lane + 32] = va[hh][1];
    }
    __syncthreads();

    // =================== FINAL: o_inner = vacc + t@Wev2 + bev2 ===================
    {
        const int col = t;
        const int h = col >> 6;
        const float bcol = bev2[col];
        #pragma unroll
        for (int i2 = 0; i2 < ITILE; i2++) {
            const float* trow = &tsh[(i2 * NH + h) * DIN];
            float acc0 = 0.f, acc1 = 0.f, acc2 = 0.f, acc3 = 0.f;
            #pragma unroll 4
            for (int cc = 0; cc < DIN; cc += 4) {
                acc0 += trow[cc]     * Wev2[(cc)     * DIN + col];
                acc1 += trow[cc + 1] * Wev2[(cc + 1) * DIN + col];
                acc2 += trow[cc + 2] * Wev2[(cc + 2) * DIN + col];
                acc3 += trow[cc + 3] * Wev2[(cc + 3) * DIN + col];
            }
            g_oi[(b * NN + i0 + i2) * DIN + col] =
                ((acc0 + acc1) + (acc2 + acc3)) + vacc[i2 * DIN + col] + bcol;
        }
    }
}

// ============================================================
extern "C" void kernel_launch(void* const* d_in, const int* in_sizes, int n_in,
                              void* d_out, int out_size)
{
    const float* x           = (const float*)d_in[0];
    const void*  mask_raw    = d_in[1];
    const float* ea          = (const float*)d_in[2];
    const float* Wq          = (const float*)d_in[3];
    const float* Wk          = (const float*)d_in[4];
    const float* Wv          = (const float*)d_in[5];
    const float* Web1        = (const float*)d_in[6];
    const float* beb1        = (const float*)d_in[7];
    const float* Web2        = (const float*)d_in[8];
    const float* beb2        = (const float*)d_in[9];
    const float* Wev1        = (const float*)d_in[10];
    const float* bev1        = (const float*)d_in[11];
    const float* Wev2        = (const float*)d_in[12];
    const float* bev2        = (const float*)d_in[13];
    const float* Wo          = (const float*)d_in[14];
    const float* bo          = (const float*)d_in[15];

    float* out = (float*)d_out;
    const int out_elems  = BB * NN * QDIM;              // 524288
    const int attn_elems = BB * NH * NN * NN;           // 2097152

    float *oip, *attn_fb;
    cudaGetSymbolAddress((void**)&oip, g_oi);
    cudaGetSymbolAddress((void**)&attn_fb, g_attn_scratch);

    const int store_attn = (out_size >= out_elems + attn_elems) ? 1 : 0;
    float* attn = store_attn ? (out + out_elems) : attn_fb;

    const int smem_bytes = 25088 * 4;   // 100352
    cudaFuncSetAttribute(attn_fused, cudaFuncAttributeMaxDynamicSharedMemorySize, smem_bytes);

    // fused q/k/v projections: 3 sel x 4 n-tiles x 16 m-tiles = 192 blocks
    qkv_gemm<<<dim3(12, (BB * NN) / 64), 256>>>(x, Wq, Wk, Wv);

    // fused attention + edge MLPs (mask handling inlined; 256 thr, 2 blocks/SM)
    attn_fused<<<dim3(NN / ITILE, BB), 256, smem_bytes>>>(
        ea, (const unsigned int*)mask_raw, Web1, beb1, Web2, beb2,
        Wev1, bev1, Wev2, bev2, attn, store_attn);

    // final projection: out = o_inner @ Wo + bo  (8 x 16 = 128 blocks, 64x64)
    gemm_tiled<<<dim3(QDIM / 64, (BB * NN) / 64), 256>>>(oip, Wo, bo, out, BB * NN, DIN, QDIM);
}